// round 7
// baseline (speedup 1.0000x reference)
#include <cuda_runtime.h>
#include <math.h>
#include <stdint.h>

// x:(4,256,32,32,32) f32 | qkv_weight:(512,256) | relative:(64,63) | gamma,beta:(512)
// m-order: m = b*1024 + w*32 + t (u = w*32+t). Legal permutation of reference n
// (attention is per-n, BN stats order-invariant); makes GEMM input reads AND
// final output writes fully contiguous, so no un-permutation is ever needed.
//
// Buffer aliasing (reduces static device mem 768MB -> 512MB):
//   g_bufA: holds qkv [b][l][o][u] (k_gemm -> k_tr), then st [m][ch][i] (k_attn -> end)
//   g_bufB: holds qkvT [m][o][l]   (k_tr -> k_attn)
// Lifetimes are disjoint: qkv is dead once k_tr finishes, st is born in k_attn.

__device__ float  g_bufA[67108864];  // qkv: ((b*32+l)*512+o)*1024+u | st: (m*512+ch)*32+i
__device__ float  g_bufB[67108864];  // qkvT: (m*512+o)*32+l
__device__ float2 g_part[512 * 8];
__device__ float2 g_stats[512];

// ---------------- 1) QKV GEMM: out[o][u] = sum_c W[o][c] * X[c][u], per (b,l) -----
__global__ __launch_bounds__(256) void k_gemm(const float* __restrict__ x,
                                              const float* __restrict__ W) {
    const int b = blockIdx.z >> 5, l = blockIdx.z & 31;
    const int u0 = blockIdx.x * 128, o0 = blockIdx.y * 128;
    const float* __restrict__ X = x + (size_t)b * 8388608 + l * 1024; // X[c*32768+u]

    __shared__ __align__(16) float As[16][128];
    __shared__ __align__(16) float Bs[16][128];

    const int tid = threadIdx.x;
    const int tx = tid & 15, ty = tid >> 4;
    const int a_o = tid >> 1, a_c = (tid & 1) * 8;
    const int b_c = ty, b_u = (tid & 15) * 8;

    float acc[8][8];
#pragma unroll
    for (int i = 0; i < 8; i++)
#pragma unroll
        for (int j = 0; j < 8; j++) acc[i][j] = 0.f;

    for (int k0 = 0; k0 < 256; k0 += 16) {
        const float* wp = W + (o0 + a_o) * 256 + k0 + a_c;
        float4 a0 = *(const float4*)wp;
        float4 a1 = *(const float4*)(wp + 4);
        const float* xp = X + (size_t)(k0 + b_c) * 32768 + u0 + b_u;
        float4 b0 = *(const float4*)xp;
        float4 b1 = *(const float4*)(xp + 4);

        As[a_c + 0][a_o] = a0.x; As[a_c + 1][a_o] = a0.y;
        As[a_c + 2][a_o] = a0.z; As[a_c + 3][a_o] = a0.w;
        As[a_c + 4][a_o] = a1.x; As[a_c + 5][a_o] = a1.y;
        As[a_c + 6][a_o] = a1.z; As[a_c + 7][a_o] = a1.w;
        *(float4*)&Bs[b_c][b_u]     = b0;
        *(float4*)&Bs[b_c][b_u + 4] = b1;
        __syncthreads();

#pragma unroll
        for (int kk = 0; kk < 16; kk++) {
            float a[8], bb[8];
            *(float4*)(a)      = *(const float4*)&As[kk][ty * 8];
            *(float4*)(a + 4)  = *(const float4*)&As[kk][ty * 8 + 4];
            *(float4*)(bb)     = *(const float4*)&Bs[kk][tx * 8];
            *(float4*)(bb + 4) = *(const float4*)&Bs[kk][tx * 8 + 4];
#pragma unroll
            for (int i = 0; i < 8; i++)
#pragma unroll
                for (int j = 0; j < 8; j++) acc[i][j] = fmaf(a[i], bb[j], acc[i][j]);
        }
        __syncthreads();
    }

    float* out = g_bufA + (size_t)blockIdx.z * 524288;
#pragma unroll
    for (int i = 0; i < 8; i++) {
        float* p = out + (size_t)(o0 + ty * 8 + i) * 1024 + u0 + tx * 8;
        *(float4*)p       = make_float4(acc[i][0], acc[i][1], acc[i][2], acc[i][3]);
        *(float4*)(p + 4) = make_float4(acc[i][4], acc[i][5], acc[i][6], acc[i][7]);
    }
}

// ---------------- 2) transpose [b][l][o][u] -> [m][o][l] -------------------------
__global__ __launch_bounds__(256) void k_tr() {
    __shared__ float tile[32][33];
    const int u0 = blockIdx.x * 32, o = blockIdx.y, b = blockIdx.z;
    const int tx = threadIdx.x & 31, ty = threadIdx.x >> 5;
    const float* src = g_bufA + (size_t)b * 16777216 + (size_t)o * 1024 + u0;
#pragma unroll
    for (int r = 0; r < 4; r++) {
        int l = ty + r * 8;
        tile[l][tx] = src[(size_t)l * 524288 + tx];
    }
    __syncthreads();
    float* dst = g_bufB + ((size_t)(b * 1024 + u0) * 512 + o) * 32;
#pragma unroll
    for (int r = 0; r < 4; r++) {
        int uu = ty + r * 8;
        dst[(size_t)uu * 16384 + tx] = tile[tx][uu];
    }
}

// ---------------- 3) attention: one m per block, warp=head (x2) -------------------
__global__ __launch_bounds__(128) void k_attn(const float* __restrict__ rel) {
    __shared__ float rel_s[64 * 63];                 // rel_s[c*63 + d], d=i+j
    __shared__ __align__(16) float kv_s[4][48 * 32]; // k rows 0..15, v rows 16..47
    const int m = blockIdx.x;
    const int warp = threadIdx.x >> 5, lane = threadIdx.x & 31; // lane = i

    for (int t = threadIdx.x; t < 64 * 63; t += 128) rel_s[t] = rel[t];
    __syncthreads();

    float* kv = kv_s[warp];
    for (int hh = 0; hh < 2; hh++) {
        const int h = warp + hh * 4;
        const float* src = g_bufB + ((size_t)m * 512 + h * 64) * 32;

        __syncwarp();
        for (int r = 0; r < 48; r++) kv[r * 32 + lane] = src[(16 + r) * 32 + lane];
        float q_r[16];
#pragma unroll
        for (int c = 0; c < 16; c++) q_r[c] = src[c * 32 + lane];
        __syncwarp();

        float kk_r[16];
#pragma unroll
        for (int c = 0; c < 16; c++) kk_r[c] = kv[c * 32 + lane]; // k[c][i]

        float sim[32];
#pragma unroll
        for (int j = 0; j < 32; j++) sim[j] = 0.f;

#pragma unroll
        for (int c = 0; c < 16; c++) {
            const float4* krow = (const float4*)(kv + c * 32);
            const float qc = q_r[c], kc = kk_r[c];
            const float* rq = rel_s + c * 63 + lane;
            const float* rk = rel_s + (16 + c) * 63 + lane;
#pragma unroll
            for (int j4 = 0; j4 < 8; j4++) {           // qk (broadcast float4)
                float4 k4 = krow[j4];
                sim[4 * j4 + 0] = fmaf(qc, k4.x, sim[4 * j4 + 0]);
                sim[4 * j4 + 1] = fmaf(qc, k4.y, sim[4 * j4 + 1]);
                sim[4 * j4 + 2] = fmaf(qc, k4.z, sim[4 * j4 + 2]);
                sim[4 * j4 + 3] = fmaf(qc, k4.w, sim[4 * j4 + 3]);
            }
#pragma unroll
            for (int j = 0; j < 32; j++)               // qr + kr
                sim[j] = fmaf(qc, rq[j], fmaf(kc, rk[j], sim[j]));
        }

        // softmax over j (in registers, per lane i)
        float mx = sim[0];
#pragma unroll
        for (int j = 1; j < 32; j++) mx = fmaxf(mx, sim[j]);
        float s = 0.f;
#pragma unroll
        for (int j = 0; j < 32; j++) { sim[j] = __expf(sim[j] - mx); s += sim[j]; }
        const float inv = 1.f / s;
#pragma unroll
        for (int j = 0; j < 32; j++) sim[j] *= inv;

        // sv / sve
        float* outp = g_bufA + ((size_t)m * 512 + h * 64) * 32 + lane;
#pragma unroll 4
        for (int c = 0; c < 32; c++) {
            const float4* vrow = (const float4*)(kv + (16 + c) * 32);
            float a = 0.f;
#pragma unroll
            for (int j4 = 0; j4 < 8; j4++) {
                float4 v4 = vrow[j4];
                a = fmaf(sim[4 * j4 + 0], v4.x, a);
                a = fmaf(sim[4 * j4 + 1], v4.y, a);
                a = fmaf(sim[4 * j4 + 2], v4.z, a);
                a = fmaf(sim[4 * j4 + 3], v4.w, a);
            }
            const float* rv = rel_s + (32 + c) * 63 + lane;
            float e = 0.f;
#pragma unroll
            for (int j = 0; j < 32; j++) e = fmaf(sim[j], rv[j], e);
            outp[(2 * c) * 32]     = a;
            outp[(2 * c + 1) * 32] = e;
        }
    }
}

// ---------------- 4) BN partial stats (deterministic, no atomics) -----------------
__global__ __launch_bounds__(256) void k_stats1() {
    const int ch = blockIdx.x, seg = blockIdx.y;
    const int w = threadIdx.x >> 5, lane = threadIdx.x & 31;
    float s = 0.f, q = 0.f;
    const int m0 = seg * 512;
    for (int t = 0; t < 64; t++) {
        const int m = m0 + w + t * 8;
        const float v = g_bufA[((size_t)m * 512 + ch) * 32 + lane];
        s += v; q = fmaf(v, v, q);
    }
#pragma unroll
    for (int o = 16; o; o >>= 1) {
        s += __shfl_down_sync(0xffffffffu, s, o);
        q += __shfl_down_sync(0xffffffffu, q, o);
    }
    __shared__ float ss[8], qs[8];
    if (lane == 0) { ss[w] = s; qs[w] = q; }
    __syncthreads();
    if (threadIdx.x == 0) {
        float S = 0.f, Q = 0.f;
        for (int t = 0; t < 8; t++) { S += ss[t]; Q += qs[t]; }
        g_part[ch * 8 + seg] = make_float2(S, Q);
    }
}

// ---------------- 5) finalize stats -> (scale, shift) -----------------------------
__global__ void k_stats2(const float* __restrict__ gamma, const float* __restrict__ beta) {
    const int ch = blockIdx.x * 32 + threadIdx.x;
    double s = 0.0, q = 0.0;
    for (int t = 0; t < 8; t++) { float2 p = g_part[ch * 8 + t]; s += p.x; q += p.y; }
    const double N = 131072.0;
    const double mean = s / N;
    const double var = q / N - mean * mean;
    const float sc = (float)((double)gamma[ch] * rsqrt(var + 1e-5));
    g_stats[ch] = make_float2(sc, (float)((double)beta[ch] - mean * (double)sc));
}

// ---------------- 6) normalize + pair-sum + transpose to output -------------------
__global__ __launch_bounds__(256) void k_out(float* __restrict__ out) {
    __shared__ float tile[32][33];
    const int u0 = blockIdx.x * 32, c = blockIdx.y, b = blockIdx.z;
    const int tx = threadIdx.x & 31, ty = threadIdx.x >> 5;
    const float2 p0 = g_stats[2 * c], p1 = g_stats[2 * c + 1];
    const float* base = g_bufA + ((size_t)(b * 1024 + u0) * 512 + 2 * c) * 32;
#pragma unroll
    for (int r = 0; r < 4; r++) {
        const int uu = ty + r * 8;
        const float* pp = base + (size_t)uu * 16384;
        tile[uu][tx] = fmaf(pp[tx], p0.x, p0.y) + fmaf(pp[32 + tx], p1.x, p1.y);
    }
    __syncthreads();
    float* op = out + (size_t)(b * 256 + c) * 32768 + u0;
#pragma unroll
    for (int r = 0; r < 4; r++) {
        const int l = ty + r * 8;
        op[(size_t)l * 1024 + tx] = tile[tx][l];
    }
}

extern "C" void kernel_launch(void* const* d_in, const int* in_sizes, int n_in,
                              void* d_out, int out_size) {
    const float* x     = (const float*)d_in[0];
    const float* Wq    = (const float*)d_in[1];
    const float* rel   = (const float*)d_in[2];
    const float* gamma = (const float*)d_in[3];
    const float* beta  = (const float*)d_in[4];
    float* out = (float*)d_out;

    k_gemm  <<<dim3(8, 4, 128), 256>>>(x, Wq);
    k_tr    <<<dim3(32, 512, 4), 256>>>();
    k_attn  <<<4096, 128>>>(rel);
    k_stats1<<<dim3(512, 8), 256>>>();
    k_stats2<<<16, 32>>>(gamma, beta);
    k_out   <<<dim3(32, 256, 4), 256>>>(out);
}

// round 10
// speedup vs baseline: 1.2418x; 1.2418x over previous
#include <cuda_runtime.h>
#include <cuda_bf16.h>
#include <math.h>
#include <stdint.h>

// x:(4,256,32,32,32) f32 | qkv_weight:(512,256) | relative:(64,63) | gamma,beta:(512)
// m-order: m = b*1024 + w*32 + t (u = w*32+t). Legal permutation of reference n.
// GEMM on classic tensor-core path (mma.sync bf16, split precision:
// W*X ~= Wh*Xh + Wl*Xh + Wh*Xl). tcgen05 is unavailable: harness targets sm_103 (no 'a').

__device__ float  g_bufA[67108864];  // qkv: ((b*32+l)*512+o)*1024+u | st: (m*512+ch)*32+i
__device__ float  g_bufB[67108864];  // qkvT: (m*512+o)*32+l
__device__ __nv_bfloat16 g_xh[33554432]; // xT hi: (bl*1024+u)*256 + c
__device__ __nv_bfloat16 g_xl[33554432]; // xT lo
__device__ __nv_bfloat16 g_wh[131072];   // W hi: [o][c]
__device__ __nv_bfloat16 g_wl[131072];   // W lo
__device__ float2 g_part[512 * 8];
__device__ float2 g_stats[512];

// ---------------- helpers ---------------------------------------------------------
__device__ __forceinline__ uint32_t smem_u32(const void* p) {
    uint32_t a;
    asm("{ .reg .u64 t; cvta.to.shared.u64 t, %1; cvt.u32.u64 %0, t; }" : "=r"(a) : "l"(p));
    return a;
}
__device__ __forceinline__ void ldm_x4(uint32_t* r, uint32_t addr) {
    asm volatile("ldmatrix.sync.aligned.m8n8.x4.shared.b16 {%0,%1,%2,%3}, [%4];"
        : "=r"(r[0]), "=r"(r[1]), "=r"(r[2]), "=r"(r[3]) : "r"(addr));
}
__device__ __forceinline__ void mma16816(float* d, const uint32_t* a, const uint32_t* b) {
    asm volatile("mma.sync.aligned.m16n8k16.row.col.f32.bf16.bf16.f32 "
        "{%0,%1,%2,%3}, {%4,%5,%6,%7}, {%8,%9}, {%0,%1,%2,%3};"
        : "+f"(d[0]), "+f"(d[1]), "+f"(d[2]), "+f"(d[3])
        : "r"(a[0]), "r"(a[1]), "r"(a[2]), "r"(a[3]), "r"(b[0]), "r"(b[1]));
}
#define SW128(o) ((o) ^ ((((uint32_t)(o)) >> 3) & 0x70))

// ---------------- 0a) W -> bf16 hi/lo ---------------------------------------------
__global__ void k_prep_w(const float* __restrict__ W) {
    int i = blockIdx.x * 256 + threadIdx.x;
    if (i < 131072) {
        float f = W[i];
        __nv_bfloat16 h = __float2bfloat16(f);
        g_wh[i] = h;
        g_wl[i] = __float2bfloat16(f - __bfloat162float(h));
    }
}

// ---------------- 0b) x -> transposed bf16 hi/lo: [bl][u][c] ----------------------
__global__ __launch_bounds__(256) void k_prep_x(const float* __restrict__ x) {
    __shared__ float tile[32][33];
    const int u0 = blockIdx.x * 32, c0 = blockIdx.y * 32, bl = blockIdx.z;
    const int b = bl >> 5, l = bl & 31;
    const float* src = x + ((size_t)(b * 256 + c0) * 32 + l) * 1024 + u0;
    for (int idx = threadIdx.x; idx < 1024; idx += 256) {
        int cc = idx >> 5, uu = idx & 31;
        tile[cc][uu] = src[(size_t)cc * 32768 + uu];
    }
    __syncthreads();
    for (int idx = threadIdx.x; idx < 512; idx += 256) {
        int uu = idx >> 4, cp = idx & 15;
        float f0 = tile[2 * cp][uu], f1 = tile[2 * cp + 1][uu];
        __nv_bfloat16 h0 = __float2bfloat16(f0), h1 = __float2bfloat16(f1);
        __nv_bfloat16 e0 = __float2bfloat16(f0 - __bfloat162float(h0));
        __nv_bfloat16 e1 = __float2bfloat16(f1 - __bfloat162float(h1));
        size_t off = ((size_t)bl * 1024 + u0 + uu) * 256 + c0 + 2 * cp;
        __nv_bfloat162 hh; hh.x = h0; hh.y = h1;
        __nv_bfloat162 ll; ll.x = e0; ll.y = e1;
        *(__nv_bfloat162*)(g_xh + off) = hh;
        *(__nv_bfloat162*)(g_xl + off) = ll;
    }
}

// ---------------- 1) QKV GEMM via mma.sync bf16 -----------------------------------
// C[o][u] = sum_c W[o][c]*X[u][c] per bl. CTA tile 128x128, warp tile 32(o)x64(u).
// smem: Ah,Al (128x64 bf16, SW128 128B rows) then Bh,Bl. 64KB dynamic.
#define SA_H 0
#define SA_L 16384
#define SB_H 32768
#define SB_L 49152
#define SM_TOTAL 65536

__global__ __launch_bounds__(256) void k_gemm_mma() {
    extern __shared__ __align__(1024) char smem[];
    const uint32_t sb = smem_u32(smem);
    const int tid = threadIdx.x, wid = tid >> 5, lane = tid & 31;
    const int bl = blockIdx.z;
    const int u0 = blockIdx.x * 128, o0 = blockIdx.y * 128;
    const int warp_m = wid & 3, warp_n = wid >> 2;  // 4 x 2 warps

    float acc[2][8][4];
#pragma unroll
    for (int mi = 0; mi < 2; mi++)
#pragma unroll
        for (int nj = 0; nj < 8; nj++)
#pragma unroll
            for (int r = 0; r < 4; r++) acc[mi][nj][r] = 0.f;

    // ldmatrix source addresses (constant across chunks except ks offset)
    const uint32_t a_row = warp_m * 32 + (lane & 15);
    const uint32_t a_cb  = (lane >> 4) << 4;              // 0 or 16 bytes
    const uint32_t b_cb  = ((lane >> 3) & 1) << 4;
    const uint32_t b_rbase = warp_n * 64 + ((lane >> 4) << 3) + (lane & 7);

    for (int kc = 0; kc < 4; kc++) {
        const int k0 = kc * 64;
        // ---- fill smem chunk: 4 buffers x 128 rows x 64 bf16 ----
#pragma unroll
        for (int it = 0; it < 4; it++) {
            const int id = tid + it * 256;            // 0..1023
            const int row = id >> 3, seg = id & 7;    // 8 x 16B = one 128B row
            const uint32_t so = SW128(row * 128 + seg * 16);
            const size_t aoff = (size_t)(o0 + row) * 256 + k0 + seg * 8;
            const size_t boff = ((size_t)bl * 1024 + u0 + row) * 256 + k0 + seg * 8;
            *(uint4*)(smem + SA_H + so) = *(const uint4*)(g_wh + aoff);
            *(uint4*)(smem + SA_L + so) = *(const uint4*)(g_wl + aoff);
            *(uint4*)(smem + SB_H + so) = *(const uint4*)(g_xh + boff);
            *(uint4*)(smem + SB_L + so) = *(const uint4*)(g_xl + boff);
        }
        __syncthreads();

#pragma unroll
        for (int ks = 0; ks < 4; ks++) {
            const uint32_t kb = ks * 32;
            uint32_t ah[2][4], al[2][4];
#pragma unroll
            for (int mi = 0; mi < 2; mi++) {
                const uint32_t off = SW128((a_row + mi * 16) * 128 + kb + a_cb);
                ldm_x4(ah[mi], sb + SA_H + off);
                ldm_x4(al[mi], sb + SA_L + off);
            }
            uint32_t bh[4][4], blo[4][4];
#pragma unroll
            for (int nj = 0; nj < 4; nj++) {
                const uint32_t off = SW128((b_rbase + nj * 16) * 128 + kb + b_cb);
                ldm_x4(bh[nj], sb + SB_H + off);
                ldm_x4(blo[nj], sb + SB_L + off);
            }
#pragma unroll
            for (int mi = 0; mi < 2; mi++)
#pragma unroll
                for (int nj = 0; nj < 4; nj++) {
                    mma16816(acc[mi][2 * nj],     ah[mi], &bh[nj][0]);
                    mma16816(acc[mi][2 * nj + 1], ah[mi], &bh[nj][2]);
                    mma16816(acc[mi][2 * nj],     al[mi], &bh[nj][0]);
                    mma16816(acc[mi][2 * nj + 1], al[mi], &bh[nj][2]);
                    mma16816(acc[mi][2 * nj],     ah[mi], &blo[nj][0]);
                    mma16816(acc[mi][2 * nj + 1], ah[mi], &blo[nj][2]);
                }
        }
        __syncthreads();
    }

    // ---- epilogue: D fragment -> g_bufA[bl][o][u] ----
    const int group = lane >> 2, tid4 = lane & 3;
    float* base = g_bufA + (size_t)bl * 524288;
#pragma unroll
    for (int mi = 0; mi < 2; mi++) {
        const int o_lo = o0 + warp_m * 32 + mi * 16 + group;
#pragma unroll
        for (int nj = 0; nj < 8; nj++) {
            const int u = u0 + warp_n * 64 + nj * 8 + tid4 * 2;
            *(float2*)(base + (size_t)o_lo * 1024 + u) =
                make_float2(acc[mi][nj][0], acc[mi][nj][1]);
            *(float2*)(base + (size_t)(o_lo + 8) * 1024 + u) =
                make_float2(acc[mi][nj][2], acc[mi][nj][3]);
        }
    }
}

// ---------------- 2) transpose [b][l][o][u] -> [m][o][l] -------------------------
__global__ __launch_bounds__(256) void k_tr() {
    __shared__ float tile[32][33];
    const int u0 = blockIdx.x * 32, o = blockIdx.y, b = blockIdx.z;
    const int tx = threadIdx.x & 31, ty = threadIdx.x >> 5;
    const float* src = g_bufA + (size_t)b * 16777216 + (size_t)o * 1024 + u0;
#pragma unroll
    for (int r = 0; r < 4; r++) {
        int l = ty + r * 8;
        tile[l][tx] = src[(size_t)l * 524288 + tx];
    }
    __syncthreads();
    float* dst = g_bufB + ((size_t)(b * 1024 + u0) * 512 + o) * 32;
#pragma unroll
    for (int r = 0; r < 4; r++) {
        int uu = ty + r * 8;
        dst[(size_t)uu * 16384 + tx] = tile[tx][uu];
    }
}

// ---------------- 3) attention: one m per block, warp=head (x2) -------------------
__global__ __launch_bounds__(128) void k_attn(const float* __restrict__ rel) {
    __shared__ float rel_s[64 * 63];
    __shared__ __align__(16) float kv_s[4][48 * 32];
    const int m = blockIdx.x;
    const int warp = threadIdx.x >> 5, lane = threadIdx.x & 31;

    for (int t = threadIdx.x; t < 64 * 63; t += 128) rel_s[t] = rel[t];
    __syncthreads();

    float* kv = kv_s[warp];
    for (int hh = 0; hh < 2; hh++) {
        const int h = warp + hh * 4;
        const float* src = g_bufB + ((size_t)m * 512 + h * 64) * 32;

        __syncwarp();
        for (int r = 0; r < 48; r++) kv[r * 32 + lane] = src[(16 + r) * 32 + lane];
        float q_r[16];
#pragma unroll
        for (int c = 0; c < 16; c++) q_r[c] = src[c * 32 + lane];
        __syncwarp();

        float kk_r[16];
#pragma unroll
        for (int c = 0; c < 16; c++) kk_r[c] = kv[c * 32 + lane];

        float sim[32];
#pragma unroll
        for (int j = 0; j < 32; j++) sim[j] = 0.f;

#pragma unroll
        for (int c = 0; c < 16; c++) {
            const float4* krow = (const float4*)(kv + c * 32);
            const float qc = q_r[c], kc = kk_r[c];
            const float* rq = rel_s + c * 63 + lane;
            const float* rk = rel_s + (16 + c) * 63 + lane;
#pragma unroll
            for (int j4 = 0; j4 < 8; j4++) {
                float4 k4 = krow[j4];
                sim[4 * j4 + 0] = fmaf(qc, k4.x, sim[4 * j4 + 0]);
                sim[4 * j4 + 1] = fmaf(qc, k4.y, sim[4 * j4 + 1]);
                sim[4 * j4 + 2] = fmaf(qc, k4.z, sim[4 * j4 + 2]);
                sim[4 * j4 + 3] = fmaf(qc, k4.w, sim[4 * j4 + 3]);
            }
#pragma unroll
            for (int j = 0; j < 32; j++)
                sim[j] = fmaf(qc, rq[j], fmaf(kc, rk[j], sim[j]));
        }

        float mx = sim[0];
#pragma unroll
        for (int j = 1; j < 32; j++) mx = fmaxf(mx, sim[j]);
        float s = 0.f;
#pragma unroll
        for (int j = 0; j < 32; j++) { sim[j] = __expf(sim[j] - mx); s += sim[j]; }
        const float inv = 1.f / s;
#pragma unroll
        for (int j = 0; j < 32; j++) sim[j] *= inv;

        float* outp = g_bufA + ((size_t)m * 512 + h * 64) * 32 + lane;
#pragma unroll 4
        for (int c = 0; c < 32; c++) {
            const float4* vrow = (const float4*)(kv + (16 + c) * 32);
            float a = 0.f;
#pragma unroll
            for (int j4 = 0; j4 < 8; j4++) {
                float4 v4 = vrow[j4];
                a = fmaf(sim[4 * j4 + 0], v4.x, a);
                a = fmaf(sim[4 * j4 + 1], v4.y, a);
                a = fmaf(sim[4 * j4 + 2], v4.z, a);
                a = fmaf(sim[4 * j4 + 3], v4.w, a);
            }
            const float* rv = rel_s + (32 + c) * 63 + lane;
            float e = 0.f;
#pragma unroll
            for (int j = 0; j < 32; j++) e = fmaf(sim[j], rv[j], e);
            outp[(2 * c) * 32]     = a;
            outp[(2 * c + 1) * 32] = e;
        }
    }
}

// ---------------- 4) BN partial stats ---------------------------------------------
__global__ __launch_bounds__(256) void k_stats1() {
    const int ch = blockIdx.x, seg = blockIdx.y;
    const int w = threadIdx.x >> 5, lane = threadIdx.x & 31;
    float s = 0.f, q = 0.f;
    const int m0 = seg * 512;
    for (int t = 0; t < 64; t++) {
        const int m = m0 + w + t * 8;
        const float v = g_bufA[((size_t)m * 512 + ch) * 32 + lane];
        s += v; q = fmaf(v, v, q);
    }
#pragma unroll
    for (int o = 16; o; o >>= 1) {
        s += __shfl_down_sync(0xffffffffu, s, o);
        q += __shfl_down_sync(0xffffffffu, q, o);
    }
    __shared__ float ss[8], qs[8];
    if (lane == 0) { ss[w] = s; qs[w] = q; }
    __syncthreads();
    if (threadIdx.x == 0) {
        float S = 0.f, Q = 0.f;
        for (int t = 0; t < 8; t++) { S += ss[t]; Q += qs[t]; }
        g_part[ch * 8 + seg] = make_float2(S, Q);
    }
}

// ---------------- 5) finalize stats ------------------------------------------------
__global__ void k_stats2(const float* __restrict__ gamma, const float* __restrict__ beta) {
    const int ch = blockIdx.x * 32 + threadIdx.x;
    double s = 0.0, q = 0.0;
    for (int t = 0; t < 8; t++) { float2 p = g_part[ch * 8 + t]; s += p.x; q += p.y; }
    const double N = 131072.0;
    const double mean = s / N;
    const double var = q / N - mean * mean;
    const float sc = (float)((double)gamma[ch] * rsqrt(var + 1e-5));
    g_stats[ch] = make_float2(sc, (float)((double)beta[ch] - mean * (double)sc));
}

// ---------------- 6) normalize + pair-sum + transpose out -------------------------
__global__ __launch_bounds__(256) void k_out(float* __restrict__ out) {
    __shared__ float tile[32][33];
    const int u0 = blockIdx.x * 32, c = blockIdx.y, b = blockIdx.z;
    const int tx = threadIdx.x & 31, ty = threadIdx.x >> 5;
    const float2 p0 = g_stats[2 * c], p1 = g_stats[2 * c + 1];
    const float* base = g_bufA + ((size_t)(b * 1024 + u0) * 512 + 2 * c) * 32;
#pragma unroll
    for (int r = 0; r < 4; r++) {
        const int uu = ty + r * 8;
        const float* pp = base + (size_t)uu * 16384;
        tile[uu][tx] = fmaf(pp[tx], p0.x, p0.y) + fmaf(pp[32 + tx], p1.x, p1.y);
    }
    __syncthreads();
    float* op = out + (size_t)(b * 256 + c) * 32768 + u0;
#pragma unroll
    for (int r = 0; r < 4; r++) {
        const int l = ty + r * 8;
        op[(size_t)l * 1024 + tx] = tile[tx][l];
    }
}

extern "C" void kernel_launch(void* const* d_in, const int* in_sizes, int n_in,
                              void* d_out, int out_size) {
    const float* x     = (const float*)d_in[0];
    const float* Wq    = (const float*)d_in[1];
    const float* rel   = (const float*)d_in[2];
    const float* gamma = (const float*)d_in[3];
    const float* beta  = (const float*)d_in[4];
    float* out = (float*)d_out;

    cudaFuncSetAttribute(k_gemm_mma, cudaFuncAttributeMaxDynamicSharedMemorySize, SM_TOTAL);

    k_prep_w  <<<512, 256>>>(Wq);
    k_prep_x  <<<dim3(32, 8, 128), 256>>>(x);
    k_gemm_mma<<<dim3(8, 4, 128), 256, SM_TOTAL>>>();
    k_tr      <<<dim3(32, 512, 4), 256>>>();
    k_attn    <<<4096, 128>>>(rel);
    k_stats1  <<<dim3(512, 8), 256>>>();
    k_stats2  <<<16, 32>>>(gamma, beta);
    k_out     <<<dim3(32, 256, 4), 256>>>(out);
}

// round 11
// speedup vs baseline: 1.4439x; 1.1628x over previous
#include <cuda_runtime.h>
#include <cuda_bf16.h>
#include <math.h>
#include <stdint.h>

// x:(4,256,32,32,32) f32 | qkv_weight:(512,256) | relative:(64,63) | gamma,beta:(512)
// m-order: m = b*1024 + w*32 + t (u = w*32+t). Legal permutation of reference n.
// GEMM: mma.sync bf16 split precision (Wh*Xh + Wl*Xh + Wh*Xl), cp.async double-buffered.
// Attention: scalar fp32 with packed fma.rn.f32x2 (sm_100+ PTX, legal on plain sm_103).

__device__ float  g_bufA[67108864];  // qkv: ((b*32+l)*512+o)*1024+u | st: (m*512+ch)*32+i
__device__ float  g_bufB[67108864];  // qkvT: (m*512+o)*32+l
__device__ __nv_bfloat16 g_xh[33554432]; // xT hi: (bl*1024+u)*256 + c
__device__ __nv_bfloat16 g_xl[33554432]; // xT lo
__device__ __nv_bfloat16 g_wh[131072];   // W hi: [o][c]
__device__ __nv_bfloat16 g_wl[131072];   // W lo
__device__ float2 g_part[512 * 8];
__device__ float2 g_stats[512];

// ---------------- helpers ---------------------------------------------------------
__device__ __forceinline__ uint32_t smem_u32(const void* p) {
    uint32_t a;
    asm("{ .reg .u64 t; cvta.to.shared.u64 t, %1; cvt.u32.u64 %0, t; }" : "=r"(a) : "l"(p));
    return a;
}
__device__ __forceinline__ void ldm_x4(uint32_t* r, uint32_t addr) {
    asm volatile("ldmatrix.sync.aligned.m8n8.x4.shared.b16 {%0,%1,%2,%3}, [%4];"
        : "=r"(r[0]), "=r"(r[1]), "=r"(r[2]), "=r"(r[3]) : "r"(addr));
}
__device__ __forceinline__ void mma16816(float* d, const uint32_t* a, const uint32_t* b) {
    asm volatile("mma.sync.aligned.m16n8k16.row.col.f32.bf16.bf16.f32 "
        "{%0,%1,%2,%3}, {%4,%5,%6,%7}, {%8,%9}, {%0,%1,%2,%3};"
        : "+f"(d[0]), "+f"(d[1]), "+f"(d[2]), "+f"(d[3])
        : "r"(a[0]), "r"(a[1]), "r"(a[2]), "r"(a[3]), "r"(b[0]), "r"(b[1]));
}
__device__ __forceinline__ void cpa16(uint32_t dst, const void* src) {
    asm volatile("cp.async.ca.shared.global [%0], [%1], 16;" :: "r"(dst), "l"(src));
}
#define CPA_COMMIT() asm volatile("cp.async.commit_group;" ::: "memory")
#define CPA_WAIT(n)  asm volatile("cp.async.wait_group %0;" :: "n"(n) : "memory")

// packed f32x2 ops
__device__ __forceinline__ void fma2(uint64_t& d, uint64_t a, uint64_t b) {
    asm("fma.rn.f32x2 %0, %1, %2, %0;" : "+l"(d) : "l"(a), "l"(b));
}
__device__ __forceinline__ uint64_t pk(float lo, float hi) {
    uint64_t r; asm("mov.b64 %0, {%1,%2};" : "=l"(r) : "f"(lo), "f"(hi)); return r;
}
__device__ __forceinline__ void upk(uint64_t v, float& lo, float& hi) {
    asm("mov.b64 {%0,%1}, %2;" : "=f"(lo), "=f"(hi) : "l"(v));
}
#define SW128(o) ((o) ^ ((((uint32_t)(o)) >> 3) & 0x70))

// ---------------- 0a) W -> bf16 hi/lo ---------------------------------------------
__global__ void k_prep_w(const float* __restrict__ W) {
    int i = blockIdx.x * 256 + threadIdx.x;
    if (i < 131072) {
        float f = W[i];
        __nv_bfloat16 h = __float2bfloat16(f);
        g_wh[i] = h;
        g_wl[i] = __float2bfloat16(f - __bfloat162float(h));
    }
}

// ---------------- 0b) x -> transposed bf16 hi/lo: [bl][u][c] ----------------------
__global__ __launch_bounds__(256) void k_prep_x(const float* __restrict__ x) {
    __shared__ float tile[32][33];
    const int u0 = blockIdx.x * 32, c0 = blockIdx.y * 32, bl = blockIdx.z;
    const int b = bl >> 5, l = bl & 31;
    const float* src = x + ((size_t)(b * 256 + c0) * 32 + l) * 1024 + u0;
    for (int idx = threadIdx.x; idx < 1024; idx += 256) {
        int cc = idx >> 5, uu = idx & 31;
        tile[cc][uu] = src[(size_t)cc * 32768 + uu];
    }
    __syncthreads();
    for (int idx = threadIdx.x; idx < 512; idx += 256) {
        int uu = idx >> 4, cp = idx & 15;
        float f0 = tile[2 * cp][uu], f1 = tile[2 * cp + 1][uu];
        __nv_bfloat16 h0 = __float2bfloat16(f0), h1 = __float2bfloat16(f1);
        __nv_bfloat16 e0 = __float2bfloat16(f0 - __bfloat162float(h0));
        __nv_bfloat16 e1 = __float2bfloat16(f1 - __bfloat162float(h1));
        size_t off = ((size_t)bl * 1024 + u0 + uu) * 256 + c0 + 2 * cp;
        __nv_bfloat162 hh; hh.x = h0; hh.y = h1;
        __nv_bfloat162 ll; ll.x = e0; ll.y = e1;
        *(__nv_bfloat162*)(g_xh + off) = hh;
        *(__nv_bfloat162*)(g_xl + off) = ll;
    }
}

// ---------------- 1) QKV GEMM via mma.sync bf16, cp.async double buffer -----------
#define SA_H 0
#define SA_L 16384
#define SB_H 32768
#define SB_L 49152
#define STAGE_SZ 65536
#define SM_TOTAL 131072

__global__ __launch_bounds__(256) void k_gemm_mma() {
    extern __shared__ __align__(1024) char smem[];
    const uint32_t sb = smem_u32(smem);
    const int tid = threadIdx.x, wid = tid >> 5, lane = tid & 31;
    const int bl = blockIdx.z;
    const int u0 = blockIdx.x * 128, o0 = blockIdx.y * 128;
    const int warp_m = wid & 3, warp_n = wid >> 2;  // 4 x 2 warps

    float acc[2][8][4];
#pragma unroll
    for (int mi = 0; mi < 2; mi++)
#pragma unroll
        for (int nj = 0; nj < 8; nj++)
#pragma unroll
            for (int r = 0; r < 4; r++) acc[mi][nj][r] = 0.f;

    const uint32_t a_row = warp_m * 32 + (lane & 15);
    const uint32_t a_cb  = (lane >> 4) << 4;
    const uint32_t b_cb  = ((lane >> 3) & 1) << 4;
    const uint32_t b_rbase = warp_n * 64 + ((lane >> 4) << 3) + (lane & 7);

    // per-thread fill coordinates (16 cp.async of 16B each per stage)
    const int f_row = tid >> 1, f_seg = (tid & 1) << 2;   // rows 0..127, 2 segs of 4x16B? no:
    // simpler: reuse old mapping: 4 iterations of (row,seg)
    auto fill = [&](int kc, int stage) {
        const int k0 = kc * 64;
        const uint32_t st = sb + stage * STAGE_SZ;
#pragma unroll
        for (int it = 0; it < 4; it++) {
            const int id = tid + it * 256;
            const int row = id >> 3, seg = id & 7;
            const uint32_t so = SW128(row * 128 + seg * 16);
            const size_t aoff = (size_t)(o0 + row) * 256 + k0 + seg * 8;
            const size_t boff = ((size_t)bl * 1024 + u0 + row) * 256 + k0 + seg * 8;
            cpa16(st + SA_H + so, g_wh + aoff);
            cpa16(st + SA_L + so, g_wl + aoff);
            cpa16(st + SB_H + so, g_xh + boff);
            cpa16(st + SB_L + so, g_xl + boff);
        }
    };
    (void)f_row; (void)f_seg;

    fill(0, 0);
    CPA_COMMIT();

    for (int kc = 0; kc < 4; kc++) {
        if (kc < 3) { fill(kc + 1, (kc + 1) & 1); CPA_COMMIT(); }
        if (kc < 3) { CPA_WAIT(1); } else { CPA_WAIT(0); }
        __syncthreads();
        const uint32_t st = sb + (kc & 1) * STAGE_SZ;

#pragma unroll
        for (int ks = 0; ks < 4; ks++) {
            const uint32_t kb = ks * 32;
            uint32_t ah[2][4], al[2][4];
#pragma unroll
            for (int mi = 0; mi < 2; mi++) {
                const uint32_t off = SW128((a_row + mi * 16) * 128 + kb + a_cb);
                ldm_x4(ah[mi], st + SA_H + off);
                ldm_x4(al[mi], st + SA_L + off);
            }
            uint32_t bh[4][4], blo[4][4];
#pragma unroll
            for (int nj = 0; nj < 4; nj++) {
                const uint32_t off = SW128((b_rbase + nj * 16) * 128 + kb + b_cb);
                ldm_x4(bh[nj], st + SB_H + off);
                ldm_x4(blo[nj], st + SB_L + off);
            }
            // term-outermost: same accumulator reused only every 16 MMAs
#pragma unroll
            for (int mi = 0; mi < 2; mi++)
#pragma unroll
                for (int nj = 0; nj < 4; nj++) {
                    mma16816(acc[mi][2 * nj],     ah[mi], &bh[nj][0]);
                    mma16816(acc[mi][2 * nj + 1], ah[mi], &bh[nj][2]);
                }
#pragma unroll
            for (int mi = 0; mi < 2; mi++)
#pragma unroll
                for (int nj = 0; nj < 4; nj++) {
                    mma16816(acc[mi][2 * nj],     al[mi], &bh[nj][0]);
                    mma16816(acc[mi][2 * nj + 1], al[mi], &bh[nj][2]);
                }
#pragma unroll
            for (int mi = 0; mi < 2; mi++)
#pragma unroll
                for (int nj = 0; nj < 4; nj++) {
                    mma16816(acc[mi][2 * nj],     ah[mi], &blo[nj][0]);
                    mma16816(acc[mi][2 * nj + 1], ah[mi], &blo[nj][2]);
                }
        }
        __syncthreads();
    }

    const int group = lane >> 2, tid4 = lane & 3;
    float* base = g_bufA + (size_t)bl * 524288;
#pragma unroll
    for (int mi = 0; mi < 2; mi++) {
        const int o_lo = o0 + warp_m * 32 + mi * 16 + group;
#pragma unroll
        for (int nj = 0; nj < 8; nj++) {
            const int u = u0 + warp_n * 64 + nj * 8 + tid4 * 2;
            *(float2*)(base + (size_t)o_lo * 1024 + u) =
                make_float2(acc[mi][nj][0], acc[mi][nj][1]);
            *(float2*)(base + (size_t)(o_lo + 8) * 1024 + u) =
                make_float2(acc[mi][nj][2], acc[mi][nj][3]);
        }
    }
}

// ---------------- 2) transpose [b][l][o][u] -> [m][o][l] -------------------------
__global__ __launch_bounds__(256) void k_tr() {
    __shared__ float tile[32][33];
    const int u0 = blockIdx.x * 32, o = blockIdx.y, b = blockIdx.z;
    const int tx = threadIdx.x & 31, ty = threadIdx.x >> 5;
    const float* src = g_bufA + (size_t)b * 16777216 + (size_t)o * 1024 + u0;
#pragma unroll
    for (int r = 0; r < 4; r++) {
        int l = ty + r * 8;
        tile[l][tx] = src[(size_t)l * 524288 + tx];
    }
    __syncthreads();
    float* dst = g_bufB + ((size_t)(b * 1024 + u0) * 512 + o) * 32;
#pragma unroll
    for (int r = 0; r < 4; r++) {
        int uu = ty + r * 8;
        dst[(size_t)uu * 16384 + tx] = tile[tx][uu];
    }
}

// ---------------- 3) attention: f32x2 packed math ---------------------------------
__global__ __launch_bounds__(128) void k_attn(const float* __restrict__ rel) {
    __shared__ float rel_s[64 * 63];
    __shared__ __align__(16) float kv_s[4][48 * 32];
    const int m = blockIdx.x;
    const int warp = threadIdx.x >> 5, lane = threadIdx.x & 31; // lane = i

    for (int t = threadIdx.x; t < 64 * 63; t += 128) rel_s[t] = rel[t];
    __syncthreads();

    float* kv = kv_s[warp];
    for (int hh = 0; hh < 2; hh++) {
        const int h = warp + hh * 4;
        const float* src = g_bufB + ((size_t)m * 512 + h * 64) * 32;

        __syncwarp();
        for (int r = 0; r < 48; r++) kv[r * 32 + lane] = src[(16 + r) * 32 + lane];
        float q_r[16];
#pragma unroll
        for (int c = 0; c < 16; c++) q_r[c] = src[c * 32 + lane];
        __syncwarp();

        float kk_r[16];
#pragma unroll
        for (int c = 0; c < 16; c++) kk_r[c] = kv[c * 32 + lane];

        uint64_t sim2[16];
#pragma unroll
        for (int jp = 0; jp < 16; jp++) sim2[jp] = 0ull;

#pragma unroll
        for (int c = 0; c < 16; c++) {
            const longlong2* krow2 = (const longlong2*)(kv + c * 32);
            const float qc = q_r[c], kc = kk_r[c];
            const uint64_t qc2 = pk(qc, qc), kc2 = pk(kc, kc);
            const float* rq = rel_s + c * 63 + lane;
            const float* rk = rel_s + (16 + c) * 63 + lane;
#pragma unroll
            for (int p = 0; p < 8; p++) {              // qk: packed pairs from smem
                longlong2 kkp = krow2[p];
                fma2(sim2[2 * p],     qc2, (uint64_t)kkp.x);
                fma2(sim2[2 * p + 1], qc2, (uint64_t)kkp.y);
            }
#pragma unroll
            for (int jp = 0; jp < 16; jp++) {          // qr + kr
                fma2(sim2[jp], qc2, pk(rq[2 * jp], rq[2 * jp + 1]));
                fma2(sim2[jp], kc2, pk(rk[2 * jp], rk[2 * jp + 1]));
            }
        }

        // softmax over j (unpack, exp, repack)
        float sv_[32];
#pragma unroll
        for (int jp = 0; jp < 16; jp++) upk(sim2[jp], sv_[2 * jp], sv_[2 * jp + 1]);
        float mx = sv_[0];
#pragma unroll
        for (int j = 1; j < 32; j++) mx = fmaxf(mx, sv_[j]);
        float s = 0.f;
#pragma unroll
        for (int j = 0; j < 32; j++) { sv_[j] = __expf(sv_[j] - mx); s += sv_[j]; }
        const float inv = 1.f / s;
#pragma unroll
        for (int jp = 0; jp < 16; jp++)
            sim2[jp] = pk(sv_[2 * jp] * inv, sv_[2 * jp + 1] * inv);

        // sv / sve (packed accumulate, horizontal add at end)
        float* outp = g_bufA + ((size_t)m * 512 + h * 64) * 32 + lane;
#pragma unroll 4
        for (int c = 0; c < 32; c++) {
            const longlong2* vrow2 = (const longlong2*)(kv + (16 + c) * 32);
            uint64_t a2 = 0ull;
#pragma unroll
            for (int p = 0; p < 8; p++) {
                longlong2 vv = vrow2[p];
                fma2(a2, sim2[2 * p],     (uint64_t)vv.x);
                fma2(a2, sim2[2 * p + 1], (uint64_t)vv.y);
            }
            const float* rv = rel_s + (32 + c) * 63 + lane;
            uint64_t e2 = 0ull;
#pragma unroll
            for (int jp = 0; jp < 16; jp++)
                fma2(e2, sim2[jp], pk(rv[2 * jp], rv[2 * jp + 1]));
            float alo, ahi, elo, ehi;
            upk(a2, alo, ahi); upk(e2, elo, ehi);
            outp[(2 * c) * 32]     = alo + ahi;
            outp[(2 * c + 1) * 32] = elo + ehi;
        }
    }
}

// ---------------- 4) BN partial stats ---------------------------------------------
__global__ __launch_bounds__(256) void k_stats1() {
    const int ch = blockIdx.x, seg = blockIdx.y;
    const int w = threadIdx.x >> 5, lane = threadIdx.x & 31;
    float s = 0.f, q = 0.f;
    const int m0 = seg * 512;
    for (int t = 0; t < 64; t++) {
        const int m = m0 + w + t * 8;
        const float v = g_bufA[((size_t)m * 512 + ch) * 32 + lane];
        s += v; q = fmaf(v, v, q);
    }
#pragma unroll
    for (int o = 16; o; o >>= 1) {
        s += __shfl_down_sync(0xffffffffu, s, o);
        q += __shfl_down_sync(0xffffffffu, q, o);
    }
    __shared__ float ss[8], qs[8];
    if (lane == 0) { ss[w] = s; qs[w] = q; }
    __syncthreads();
    if (threadIdx.x == 0) {
        float S = 0.f, Q = 0.f;
        for (int t = 0; t < 8; t++) { S += ss[t]; Q += qs[t]; }
        g_part[ch * 8 + seg] = make_float2(S, Q);
    }
}

// ---------------- 5) finalize stats ------------------------------------------------
__global__ void k_stats2(const float* __restrict__ gamma, const float* __restrict__ beta) {
    const int ch = blockIdx.x * 32 + threadIdx.x;
    double s = 0.0, q = 0.0;
    for (int t = 0; t < 8; t++) { float2 p = g_part[ch * 8 + t]; s += p.x; q += p.y; }
    const double N = 131072.0;
    const double mean = s / N;
    const double var = q / N - mean * mean;
    const float sc = (float)((double)gamma[ch] * rsqrt(var + 1e-5));
    g_stats[ch] = make_float2(sc, (float)((double)beta[ch] - mean * (double)sc));
}

// ---------------- 6) normalize + pair-sum + transpose out -------------------------
__global__ __launch_bounds__(256) void k_out(float* __restrict__ out) {
    __shared__ float tile[32][33];
    const int u0 = blockIdx.x * 32, c = blockIdx.y, b = blockIdx.z;
    const int tx = threadIdx.x & 31, ty = threadIdx.x >> 5;
    const float2 p0 = g_stats[2 * c], p1 = g_stats[2 * c + 1];
    const float* base = g_bufA + ((size_t)(b * 1024 + u0) * 512 + 2 * c) * 32;
#pragma unroll
    for (int r = 0; r < 4; r++) {
        const int uu = ty + r * 8;
        const float* pp = base + (size_t)uu * 16384;
        tile[uu][tx] = fmaf(pp[tx], p0.x, p0.y) + fmaf(pp[32 + tx], p1.x, p1.y);
    }
    __syncthreads();
    float* op = out + (size_t)(b * 256 + c) * 32768 + u0;
#pragma unroll
    for (int r = 0; r < 4; r++) {
        const int l = ty + r * 8;
        op[(size_t)l * 1024 + tx] = tile[tx][l];
    }
}

extern "C" void kernel_launch(void* const* d_in, const int* in_sizes, int n_in,
                              void* d_out, int out_size) {
    const float* x     = (const float*)d_in[0];
    const float* Wq    = (const float*)d_in[1];
    const float* rel   = (const float*)d_in[2];
    const float* gamma = (const float*)d_in[3];
    const float* beta  = (const float*)d_in[4];
    float* out = (float*)d_out;

    cudaFuncSetAttribute(k_gemm_mma, cudaFuncAttributeMaxDynamicSharedMemorySize, SM_TOTAL);

    k_prep_w  <<<512, 256>>>(Wq);
    k_prep_x  <<<dim3(32, 8, 128), 256>>>(x);
    k_gemm_mma<<<dim3(8, 4, 128), 256, SM_TOTAL>>>();
    k_tr      <<<dim3(32, 512, 4), 256>>>();
    k_attn    <<<4096, 128>>>(rel);
    k_stats1  <<<dim3(512, 8), 256>>>();
    k_stats2  <<<16, 32>>>(gamma, beta);
    k_out     <<<dim3(32, 256, 4), 256>>>(out);
}

// round 14
// speedup vs baseline: 1.5034x; 1.0412x over previous
#include <cuda_runtime.h>
#include <cuda_bf16.h>
#include <math.h>
#include <stdint.h>

// x:(4,256,32,32,32) f32 | qkv_weight:(512,256) | relative:(64,63) | gamma,beta:(512)
// m-order: m = b*1024 + w*32 + t (u = w*32+t). Legal permutation of reference n.
// GEMM: mma.sync bf16 split precision (Wh*Xh + Wl*Xh + Wh*Xl), cp.async double-buffered,
//       epilogue writes attention-ready layout bufB[m][l][o] via smem transpose (k_tr deleted).
//       EPAD=132 (16B-aligned rows; 129 caused misaligned float4 LDS -> R13 trap).
// Attention: packed fma.rn.f32x2; stages [l][o] -> kvq[c][i] smem transpose (pad 36).

__device__ float  g_bufA[67108864];  // st: (m*512+ch)*32+i   (attention output)
__device__ float  g_bufB[67108864];  // qkv: ((m*32)+l)*512+o  = [m][l][o]
__device__ __nv_bfloat16 g_xh[33554432]; // xT hi: (bl*1024+u)*256 + c
__device__ __nv_bfloat16 g_xl[33554432]; // xT lo
__device__ __nv_bfloat16 g_wh[131072];   // W hi: [o][c]
__device__ __nv_bfloat16 g_wl[131072];   // W lo
__device__ float2 g_part[512 * 8];
__device__ float2 g_stats[512];

// ---------------- helpers ---------------------------------------------------------
__device__ __forceinline__ uint32_t smem_u32(const void* p) {
    uint32_t a;
    asm("{ .reg .u64 t; cvta.to.shared.u64 t, %1; cvt.u32.u64 %0, t; }" : "=r"(a) : "l"(p));
    return a;
}
__device__ __forceinline__ void ldm_x4(uint32_t* r, uint32_t addr) {
    asm volatile("ldmatrix.sync.aligned.m8n8.x4.shared.b16 {%0,%1,%2,%3}, [%4];"
        : "=r"(r[0]), "=r"(r[1]), "=r"(r[2]), "=r"(r[3]) : "r"(addr));
}
__device__ __forceinline__ void mma16816(float* d, const uint32_t* a, const uint32_t* b) {
    asm volatile("mma.sync.aligned.m16n8k16.row.col.f32.bf16.bf16.f32 "
        "{%0,%1,%2,%3}, {%4,%5,%6,%7}, {%8,%9}, {%0,%1,%2,%3};"
        : "+f"(d[0]), "+f"(d[1]), "+f"(d[2]), "+f"(d[3])
        : "r"(a[0]), "r"(a[1]), "r"(a[2]), "r"(a[3]), "r"(b[0]), "r"(b[1]));
}
__device__ __forceinline__ void cpa16(uint32_t dst, const void* src) {
    asm volatile("cp.async.ca.shared.global [%0], [%1], 16;" :: "r"(dst), "l"(src));
}
#define CPA_COMMIT() asm volatile("cp.async.commit_group;" ::: "memory")
#define CPA_WAIT(n)  asm volatile("cp.async.wait_group %0;" :: "n"(n) : "memory")

__device__ __forceinline__ void fma2(uint64_t& d, uint64_t a, uint64_t b) {
    asm("fma.rn.f32x2 %0, %1, %2, %0;" : "+l"(d) : "l"(a), "l"(b));
}
__device__ __forceinline__ uint64_t pk(float lo, float hi) {
    uint64_t r; asm("mov.b64 %0, {%1,%2};" : "=l"(r) : "f"(lo), "f"(hi)); return r;
}
__device__ __forceinline__ void upk(uint64_t v, float& lo, float& hi) {
    asm("mov.b64 {%0,%1}, %2;" : "=f"(lo), "=f"(hi) : "l"(v));
}
#define SW128(o) ((o) ^ ((((uint32_t)(o)) >> 3) & 0x70))

// ---------------- 0a) W -> bf16 hi/lo ---------------------------------------------
__global__ void k_prep_w(const float* __restrict__ W) {
    int i = blockIdx.x * 256 + threadIdx.x;
    if (i < 131072) {
        float f = W[i];
        __nv_bfloat16 h = __float2bfloat16(f);
        g_wh[i] = h;
        g_wl[i] = __float2bfloat16(f - __bfloat162float(h));
    }
}

// ---------------- 0b) x -> transposed bf16 hi/lo: [bl][u][c] ----------------------
__global__ __launch_bounds__(256) void k_prep_x(const float* __restrict__ x) {
    __shared__ float tile[32][33];
    const int u0 = blockIdx.x * 32, c0 = blockIdx.y * 32, bl = blockIdx.z;
    const int b = bl >> 5, l = bl & 31;
    const float* src = x + ((size_t)(b * 256 + c0) * 32 + l) * 1024 + u0;
    for (int idx = threadIdx.x; idx < 1024; idx += 256) {
        int cc = idx >> 5, uu = idx & 31;
        tile[cc][uu] = src[(size_t)cc * 32768 + uu];
    }
    __syncthreads();
    for (int idx = threadIdx.x; idx < 512; idx += 256) {
        int uu = idx >> 4, cp = idx & 15;
        float f0 = tile[2 * cp][uu], f1 = tile[2 * cp + 1][uu];
        __nv_bfloat16 h0 = __float2bfloat16(f0), h1 = __float2bfloat16(f1);
        __nv_bfloat16 e0 = __float2bfloat16(f0 - __bfloat162float(h0));
        __nv_bfloat16 e1 = __float2bfloat16(f1 - __bfloat162float(h1));
        size_t off = ((size_t)bl * 1024 + u0 + uu) * 256 + c0 + 2 * cp;
        __nv_bfloat162 hh; hh.x = h0; hh.y = h1;
        __nv_bfloat162 ll; ll.x = e0; ll.y = e1;
        *(__nv_bfloat162*)(g_xh + off) = hh;
        *(__nv_bfloat162*)(g_xl + off) = ll;
    }
}

// ---------------- 1) QKV GEMM via mma.sync bf16, epilogue -> bufB[m][l][o] --------
#define SA_H 0
#define SA_L 16384
#define SB_H 32768
#define SB_L 49152
#define STAGE_SZ 65536
#define SM_TOTAL 131072
#define EPAD 132

__global__ __launch_bounds__(256) void k_gemm_mma() {
    extern __shared__ __align__(1024) char smem[];
    const uint32_t sb = smem_u32(smem);
    const int tid = threadIdx.x, wid = tid >> 5, lane = tid & 31;
    const int bl = blockIdx.z, bIdx = bl >> 5, lIdx = bl & 31;
    const int u0 = blockIdx.x * 128, o0 = blockIdx.y * 128;
    const int warp_m = wid & 3, warp_n = wid >> 2;  // 4 x 2 warps

    float acc[2][8][4];
#pragma unroll
    for (int mi = 0; mi < 2; mi++)
#pragma unroll
        for (int nj = 0; nj < 8; nj++)
#pragma unroll
            for (int r = 0; r < 4; r++) acc[mi][nj][r] = 0.f;

    const uint32_t a_row = warp_m * 32 + (lane & 15);
    const uint32_t a_cb  = (lane >> 4) << 4;
    const uint32_t b_cb  = ((lane >> 3) & 1) << 4;
    const uint32_t b_rbase = warp_n * 64 + ((lane >> 4) << 3) + (lane & 7);

    auto fill = [&](int kc, int stage) {
        const int k0 = kc * 64;
        const uint32_t st = sb + stage * STAGE_SZ;
#pragma unroll
        for (int it = 0; it < 4; it++) {
            const int id = tid + it * 256;
            const int row = id >> 3, seg = id & 7;
            const uint32_t so = SW128(row * 128 + seg * 16);
            const size_t aoff = (size_t)(o0 + row) * 256 + k0 + seg * 8;
            const size_t boff = ((size_t)bl * 1024 + u0 + row) * 256 + k0 + seg * 8;
            cpa16(st + SA_H + so, g_wh + aoff);
            cpa16(st + SA_L + so, g_wl + aoff);
            cpa16(st + SB_H + so, g_xh + boff);
            cpa16(st + SB_L + so, g_xl + boff);
        }
    };

    fill(0, 0);
    CPA_COMMIT();

    for (int kc = 0; kc < 4; kc++) {
        if (kc < 3) { fill(kc + 1, (kc + 1) & 1); CPA_COMMIT(); }
        if (kc < 3) { CPA_WAIT(1); } else { CPA_WAIT(0); }
        __syncthreads();
        const uint32_t st = sb + (kc & 1) * STAGE_SZ;

#pragma unroll
        for (int ks = 0; ks < 4; ks++) {
            const uint32_t kb = ks * 32;
            uint32_t ah[2][4], al[2][4];
#pragma unroll
            for (int mi = 0; mi < 2; mi++) {
                const uint32_t off = SW128((a_row + mi * 16) * 128 + kb + a_cb);
                ldm_x4(ah[mi], st + SA_H + off);
                ldm_x4(al[mi], st + SA_L + off);
            }
            uint32_t bh[4][4], blo[4][4];
#pragma unroll
            for (int nj = 0; nj < 4; nj++) {
                const uint32_t off = SW128((b_rbase + nj * 16) * 128 + kb + b_cb);
                ldm_x4(bh[nj], st + SB_H + off);
                ldm_x4(blo[nj], st + SB_L + off);
            }
#pragma unroll
            for (int mi = 0; mi < 2; mi++)
#pragma unroll
                for (int nj = 0; nj < 4; nj++) {
                    mma16816(acc[mi][2 * nj],     ah[mi], &bh[nj][0]);
                    mma16816(acc[mi][2 * nj + 1], ah[mi], &bh[nj][2]);
                }
#pragma unroll
            for (int mi = 0; mi < 2; mi++)
#pragma unroll
                for (int nj = 0; nj < 4; nj++) {
                    mma16816(acc[mi][2 * nj],     al[mi], &bh[nj][0]);
                    mma16816(acc[mi][2 * nj + 1], al[mi], &bh[nj][2]);
                }
#pragma unroll
            for (int mi = 0; mi < 2; mi++)
#pragma unroll
                for (int nj = 0; nj < 4; nj++) {
                    mma16816(acc[mi][2 * nj],     ah[mi], &blo[nj][0]);
                    mma16816(acc[mi][2 * nj + 1], ah[mi], &blo[nj][2]);
                }
        }
        __syncthreads();
    }

    // ---- epilogue: frags -> smem[u][o] (pad 132) -> bufB[(b*1024+u)*32+l]*512+o ----
    float* sep = (float*)smem;
    const int group = lane >> 2, tid4 = lane & 3;
#pragma unroll
    for (int mi = 0; mi < 2; mi++) {
        const int oo = warp_m * 32 + mi * 16 + group;
#pragma unroll
        for (int nj = 0; nj < 8; nj++) {
            const int uu = warp_n * 64 + nj * 8 + tid4 * 2;
            sep[(size_t)uu * EPAD + oo]           = acc[mi][nj][0];
            sep[(size_t)(uu + 1) * EPAD + oo]     = acc[mi][nj][1];
            sep[(size_t)uu * EPAD + oo + 8]       = acc[mi][nj][2];
            sep[(size_t)(uu + 1) * EPAD + oo + 8] = acc[mi][nj][3];
        }
    }
    __syncthreads();
    for (int r = wid; r < 128; r += 8) {
        float4 v = *(const float4*)&sep[(size_t)r * EPAD + lane * 4];
        *(float4*)(g_bufB + (((size_t)(bIdx * 1024 + u0 + r)) * 32 + lIdx) * 512
                          + o0 + lane * 4) = v;
    }
}

// ---------------- 3) attention: reads bufB[m][l][o], f32x2 packed math ------------
#define KPAD 36
#define ATTN_SMEM ((4032 + 4 * 64 * KPAD) * 4)   // rel_s + 4 warps * kvq[64][36]

__global__ __launch_bounds__(128) void k_attn(const float* __restrict__ rel) {
    extern __shared__ __align__(16) float dsm[];
    float* rel_s = dsm;                               // [64*63]
    const int m = blockIdx.x;
    const int warp = threadIdx.x >> 5, lane = threadIdx.x & 31; // lane = i

    for (int t = threadIdx.x; t < 64 * 63; t += 128) rel_s[t] = rel[t];
    __syncthreads();

    float* kvq = dsm + 4032 + warp * (64 * KPAD);     // kvq[c][i], c=0..63 per head
    for (int hh = 0; hh < 2; hh++) {
        const int h = warp + hh * 4;
        const float* src2 = g_bufB + (size_t)m * 16384 + h * 64;   // + l*512 + c

        __syncwarp();
#pragma unroll 4
        for (int l = 0; l < 32; l++) {
            float v0 = src2[l * 512 + lane];
            float v1 = src2[l * 512 + 32 + lane];
            kvq[lane * KPAD + l]        = v0;
            kvq[(lane + 32) * KPAD + l] = v1;
        }
        __syncwarp();

        float q_r[16], kk_r[16];
#pragma unroll
        for (int c = 0; c < 16; c++) {
            q_r[c]  = kvq[c * KPAD + lane];
            kk_r[c] = kvq[(16 + c) * KPAD + lane];
        }

        uint64_t sim2[16];
#pragma unroll
        for (int jp = 0; jp < 16; jp++) sim2[jp] = 0ull;

#pragma unroll
        for (int c = 0; c < 16; c++) {
            const longlong2* krow2 = (const longlong2*)(kvq + (16 + c) * KPAD);
            const float qc = q_r[c], kc = kk_r[c];
            const uint64_t qc2 = pk(qc, qc), kc2 = pk(kc, kc);
            const float* rq = rel_s + c * 63 + lane;
            const float* rk = rel_s + (16 + c) * 63 + lane;
#pragma unroll
            for (int p = 0; p < 8; p++) {
                longlong2 kkp = krow2[p];
                fma2(sim2[2 * p],     qc2, (uint64_t)kkp.x);
                fma2(sim2[2 * p + 1], qc2, (uint64_t)kkp.y);
            }
#pragma unroll
            for (int jp = 0; jp < 16; jp++) {
                fma2(sim2[jp], qc2, pk(rq[2 * jp], rq[2 * jp + 1]));
                fma2(sim2[jp], kc2, pk(rk[2 * jp], rk[2 * jp + 1]));
            }
        }

        float sv_[32];
#pragma unroll
        for (int jp = 0; jp < 16; jp++) upk(sim2[jp], sv_[2 * jp], sv_[2 * jp + 1]);
        float mx = sv_[0];
#pragma unroll
        for (int j = 1; j < 32; j++) mx = fmaxf(mx, sv_[j]);
        float s = 0.f;
#pragma unroll
        for (int j = 0; j < 32; j++) { sv_[j] = __expf(sv_[j] - mx); s += sv_[j]; }
        const float inv = 1.f / s;
#pragma unroll
        for (int jp = 0; jp < 16; jp++)
            sim2[jp] = pk(sv_[2 * jp] * inv, sv_[2 * jp + 1] * inv);

        float* outp = g_bufA + ((size_t)m * 512 + h * 64) * 32 + lane;
#pragma unroll 4
        for (int c = 0; c < 32; c++) {
            const longlong2* vrow2 = (const longlong2*)(kvq + (32 + c) * KPAD);
            uint64_t a2 = 0ull;
#pragma unroll
            for (int p = 0; p < 8; p++) {
                longlong2 vv = vrow2[p];
                fma2(a2, sim2[2 * p],     (uint64_t)vv.x);
                fma2(a2, sim2[2 * p + 1], (uint64_t)vv.y);
            }
            const float* rv = rel_s + (32 + c) * 63 + lane;
            uint64_t e2 = 0ull;
#pragma unroll
            for (int jp = 0; jp < 16; jp++)
                fma2(e2, sim2[jp], pk(rv[2 * jp], rv[2 * jp + 1]));
            float alo, ahi, elo, ehi;
            upk(a2, alo, ahi); upk(e2, elo, ehi);
            outp[(2 * c) * 32]     = alo + ahi;
            outp[(2 * c + 1) * 32] = elo + ehi;
        }
    }
}

// ---------------- 4) BN partial stats ---------------------------------------------
__global__ __launch_bounds__(256) void k_stats1() {
    const int ch = blockIdx.x, seg = blockIdx.y;
    const int w = threadIdx.x >> 5, lane = threadIdx.x & 31;
    float s = 0.f, q = 0.f;
    const int m0 = seg * 512;
    for (int t = 0; t < 64; t++) {
        const int m = m0 + w + t * 8;
        const float v = g_bufA[((size_t)m * 512 + ch) * 32 + lane];
        s += v; q = fmaf(v, v, q);
    }
#pragma unroll
    for (int o = 16; o; o >>= 1) {
        s += __shfl_down_sync(0xffffffffu, s, o);
        q += __shfl_down_sync(0xffffffffu, q, o);
    }
    __shared__ float ss[8], qs[8];
    if (lane == 0) { ss[w] = s; qs[w] = q; }
    __syncthreads();
    if (threadIdx.x == 0) {
        float S = 0.f, Q = 0.f;
        for (int t = 0; t < 8; t++) { S += ss[t]; Q += qs[t]; }
        g_part[ch * 8 + seg] = make_float2(S, Q);
    }
}

// ---------------- 5) finalize stats ------------------------------------------------
__global__ void k_stats2(const float* __restrict__ gamma, const float* __restrict__ beta) {
    const int ch = blockIdx.x * 32 + threadIdx.x;
    double s = 0.0, q = 0.0;
    for (int t = 0; t < 8; t++) { float2 p = g_part[ch * 8 + t]; s += p.x; q += p.y; }
    const double N = 131072.0;
    const double mean = s / N;
    const double var = q / N - mean * mean;
    const float sc = (float)((double)gamma[ch] * rsqrt(var + 1e-5));
    g_stats[ch] = make_float2(sc, (float)((double)beta[ch] - mean * (double)sc));
}

// ---------------- 6) normalize + pair-sum + transpose out -------------------------
__global__ __launch_bounds__(256) void k_out(float* __restrict__ out) {
    __shared__ float tile[32][33];
    const int u0 = blockIdx.x * 32, c = blockIdx.y, b = blockIdx.z;
    const int tx = threadIdx.x & 31, ty = threadIdx.x >> 5;
    const float2 p0 = g_stats[2 * c], p1 = g_stats[2 * c + 1];
    const float* base = g_bufA + ((size_t)(b * 1024 + u0) * 512 + 2 * c) * 32;
#pragma unroll
    for (int r = 0; r < 4; r++) {
        const int uu = ty + r * 8;
        const float* pp = base + (size_t)uu * 16384;
        tile[uu][tx] = fmaf(pp[tx], p0.x, p0.y) + fmaf(pp[32 + tx], p1.x, p1.y);
    }
    __syncthreads();
    float* op = out + (size_t)(b * 256 + c) * 32768 + u0;
#pragma unroll
    for (int r = 0; r < 4; r++) {
        const int l = ty + r * 8;
        op[(size_t)l * 1024 + tx] = tile[tx][l];
    }
}

extern "C" void kernel_launch(void* const* d_in, const int* in_sizes, int n_in,
                              void* d_out, int out_size) {
    const float* x     = (const float*)d_in[0];
    const float* Wq    = (const float*)d_in[1];
    const float* rel   = (const float*)d_in[2];
    const float* gamma = (const float*)d_in[3];
    const float* beta  = (const float*)d_in[4];
    float* out = (float*)d_out;

    cudaFuncSetAttribute(k_gemm_mma, cudaFuncAttributeMaxDynamicSharedMemorySize, SM_TOTAL);
    cudaFuncSetAttribute(k_attn, cudaFuncAttributeMaxDynamicSharedMemorySize, ATTN_SMEM);

    k_prep_w  <<<512, 256>>>(Wq);
    k_prep_x  <<<dim3(32, 8, 128), 256>>>(x);
    k_gemm_mma<<<dim3(8, 4, 128), 256, SM_TOTAL>>>();
    k_attn    <<<4096, 128, ATTN_SMEM>>>(rel);
    k_stats1  <<<dim3(512, 8), 256>>>();
    k_stats2  <<<16, 32>>>(gamma, beta);
    k_out     <<<dim3(32, 256, 4), 256>>>(out);
}

// round 15
// speedup vs baseline: 1.6303x; 1.0845x over previous
#include <cuda_runtime.h>
#include <cuda_bf16.h>
#include <math.h>
#include <stdint.h>

// x:(4,256,32,32,32) f32 | qkv_weight:(512,256) | relative:(64,63) | gamma,beta:(512)
// m-order: m = b*1024 + w*32 + t (u = w*32+t). Legal permutation of reference n.
// GEMM: mma.sync bf16 split precision (Wh*Xh + Wl*Xh + Wh*Xl), cp.async double-buffered,
//       epilogue writes bufB[m][l][o] via smem transpose (EPAD=132, 16B-aligned rows).
// Attention: f32x2 packs HEAD-PAIRS (h, h+4) -> rel-table smem traffic halved
//       (crossbar-bound per R14 ncu: L1=81%). kv2 rows stride 34 float2 = 272B (16B-aligned).

__device__ float  g_bufA[67108864];  // st: (m*512+ch)*32+i   (attention output)
__device__ float  g_bufB[67108864];  // qkv: ((m*32)+l)*512+o  = [m][l][o]
__device__ __nv_bfloat16 g_xh[33554432]; // xT hi: (bl*1024+u)*256 + c
__device__ __nv_bfloat16 g_xl[33554432]; // xT lo
__device__ __nv_bfloat16 g_wh[131072];   // W hi: [o][c]
__device__ __nv_bfloat16 g_wl[131072];   // W lo
__device__ float2 g_part[512 * 8];
__device__ float2 g_stats[512];

// ---------------- helpers ---------------------------------------------------------
__device__ __forceinline__ uint32_t smem_u32(const void* p) {
    uint32_t a;
    asm("{ .reg .u64 t; cvta.to.shared.u64 t, %1; cvt.u32.u64 %0, t; }" : "=r"(a) : "l"(p));
    return a;
}
__device__ __forceinline__ void ldm_x4(uint32_t* r, uint32_t addr) {
    asm volatile("ldmatrix.sync.aligned.m8n8.x4.shared.b16 {%0,%1,%2,%3}, [%4];"
        : "=r"(r[0]), "=r"(r[1]), "=r"(r[2]), "=r"(r[3]) : "r"(addr));
}
__device__ __forceinline__ void mma16816(float* d, const uint32_t* a, const uint32_t* b) {
    asm volatile("mma.sync.aligned.m16n8k16.row.col.f32.bf16.bf16.f32 "
        "{%0,%1,%2,%3}, {%4,%5,%6,%7}, {%8,%9}, {%0,%1,%2,%3};"
        : "+f"(d[0]), "+f"(d[1]), "+f"(d[2]), "+f"(d[3])
        : "r"(a[0]), "r"(a[1]), "r"(a[2]), "r"(a[3]), "r"(b[0]), "r"(b[1]));
}
__device__ __forceinline__ void cpa16(uint32_t dst, const void* src) {
    asm volatile("cp.async.ca.shared.global [%0], [%1], 16;" :: "r"(dst), "l"(src));
}
#define CPA_COMMIT() asm volatile("cp.async.commit_group;" ::: "memory")
#define CPA_WAIT(n)  asm volatile("cp.async.wait_group %0;" :: "n"(n) : "memory")

__device__ __forceinline__ void fma2(uint64_t& d, uint64_t a, uint64_t b) {
    asm("fma.rn.f32x2 %0, %1, %2, %0;" : "+l"(d) : "l"(a), "l"(b));
}
__device__ __forceinline__ uint64_t pk(float lo, float hi) {
    uint64_t r; asm("mov.b64 %0, {%1,%2};" : "=l"(r) : "f"(lo), "f"(hi)); return r;
}
__device__ __forceinline__ void upk(uint64_t v, float& lo, float& hi) {
    asm("mov.b64 {%0,%1}, %2;" : "=f"(lo), "=f"(hi) : "l"(v));
}
#define SW128(o) ((o) ^ ((((uint32_t)(o)) >> 3) & 0x70))

// ---------------- 0a) W -> bf16 hi/lo ---------------------------------------------
__global__ void k_prep_w(const float* __restrict__ W) {
    int i = blockIdx.x * 256 + threadIdx.x;
    if (i < 131072) {
        float f = W[i];
        __nv_bfloat16 h = __float2bfloat16(f);
        g_wh[i] = h;
        g_wl[i] = __float2bfloat16(f - __bfloat162float(h));
    }
}

// ---------------- 0b) x -> transposed bf16 hi/lo: [bl][u][c] ----------------------
__global__ __launch_bounds__(256) void k_prep_x(const float* __restrict__ x) {
    __shared__ float tile[32][33];
    const int u0 = blockIdx.x * 32, c0 = blockIdx.y * 32, bl = blockIdx.z;
    const int b = bl >> 5, l = bl & 31;
    const float* src = x + ((size_t)(b * 256 + c0) * 32 + l) * 1024 + u0;
    for (int idx = threadIdx.x; idx < 1024; idx += 256) {
        int cc = idx >> 5, uu = idx & 31;
        tile[cc][uu] = src[(size_t)cc * 32768 + uu];
    }
    __syncthreads();
    for (int idx = threadIdx.x; idx < 512; idx += 256) {
        int uu = idx >> 4, cp = idx & 15;
        float f0 = tile[2 * cp][uu], f1 = tile[2 * cp + 1][uu];
        __nv_bfloat16 h0 = __float2bfloat16(f0), h1 = __float2bfloat16(f1);
        __nv_bfloat16 e0 = __float2bfloat16(f0 - __bfloat162float(h0));
        __nv_bfloat16 e1 = __float2bfloat16(f1 - __bfloat162float(h1));
        size_t off = ((size_t)bl * 1024 + u0 + uu) * 256 + c0 + 2 * cp;
        __nv_bfloat162 hh; hh.x = h0; hh.y = h1;
        __nv_bfloat162 ll; ll.x = e0; ll.y = e1;
        *(__nv_bfloat162*)(g_xh + off) = hh;
        *(__nv_bfloat162*)(g_xl + off) = ll;
    }
}

// ---------------- 1) QKV GEMM via mma.sync bf16, epilogue -> bufB[m][l][o] --------
#define SA_H 0
#define SA_L 16384
#define SB_H 32768
#define SB_L 49152
#define STAGE_SZ 65536
#define SM_TOTAL 131072
#define EPAD 132

__global__ __launch_bounds__(256) void k_gemm_mma() {
    extern __shared__ __align__(1024) char smem[];
    const uint32_t sb = smem_u32(smem);
    const int tid = threadIdx.x, wid = tid >> 5, lane = tid & 31;
    const int bl = blockIdx.z, bIdx = bl >> 5, lIdx = bl & 31;
    const int u0 = blockIdx.x * 128, o0 = blockIdx.y * 128;
    const int warp_m = wid & 3, warp_n = wid >> 2;  // 4 x 2 warps

    float acc[2][8][4];
#pragma unroll
    for (int mi = 0; mi < 2; mi++)
#pragma unroll
        for (int nj = 0; nj < 8; nj++)
#pragma unroll
            for (int r = 0; r < 4; r++) acc[mi][nj][r] = 0.f;

    const uint32_t a_row = warp_m * 32 + (lane & 15);
    const uint32_t a_cb  = (lane >> 4) << 4;
    const uint32_t b_cb  = ((lane >> 3) & 1) << 4;
    const uint32_t b_rbase = warp_n * 64 + ((lane >> 4) << 3) + (lane & 7);

    auto fill = [&](int kc, int stage) {
        const int k0 = kc * 64;
        const uint32_t st = sb + stage * STAGE_SZ;
#pragma unroll
        for (int it = 0; it < 4; it++) {
            const int id = tid + it * 256;
            const int row = id >> 3, seg = id & 7;
            const uint32_t so = SW128(row * 128 + seg * 16);
            const size_t aoff = (size_t)(o0 + row) * 256 + k0 + seg * 8;
            const size_t boff = ((size_t)bl * 1024 + u0 + row) * 256 + k0 + seg * 8;
            cpa16(st + SA_H + so, g_wh + aoff);
            cpa16(st + SA_L + so, g_wl + aoff);
            cpa16(st + SB_H + so, g_xh + boff);
            cpa16(st + SB_L + so, g_xl + boff);
        }
    };

    fill(0, 0);
    CPA_COMMIT();

    for (int kc = 0; kc < 4; kc++) {
        if (kc < 3) { fill(kc + 1, (kc + 1) & 1); CPA_COMMIT(); }
        if (kc < 3) { CPA_WAIT(1); } else { CPA_WAIT(0); }
        __syncthreads();
        const uint32_t st = sb + (kc & 1) * STAGE_SZ;

#pragma unroll
        for (int ks = 0; ks < 4; ks++) {
            const uint32_t kb = ks * 32;
            uint32_t ah[2][4], al[2][4];
#pragma unroll
            for (int mi = 0; mi < 2; mi++) {
                const uint32_t off = SW128((a_row + mi * 16) * 128 + kb + a_cb);
                ldm_x4(ah[mi], st + SA_H + off);
                ldm_x4(al[mi], st + SA_L + off);
            }
            uint32_t bh[4][4], blo[4][4];
#pragma unroll
            for (int nj = 0; nj < 4; nj++) {
                const uint32_t off = SW128((b_rbase + nj * 16) * 128 + kb + b_cb);
                ldm_x4(bh[nj], st + SB_H + off);
                ldm_x4(blo[nj], st + SB_L + off);
            }
#pragma unroll
            for (int mi = 0; mi < 2; mi++)
#pragma unroll
                for (int nj = 0; nj < 4; nj++) {
                    mma16816(acc[mi][2 * nj],     ah[mi], &bh[nj][0]);
                    mma16816(acc[mi][2 * nj + 1], ah[mi], &bh[nj][2]);
                }
#pragma unroll
            for (int mi = 0; mi < 2; mi++)
#pragma unroll
                for (int nj = 0; nj < 4; nj++) {
                    mma16816(acc[mi][2 * nj],     al[mi], &bh[nj][0]);
                    mma16816(acc[mi][2 * nj + 1], al[mi], &bh[nj][2]);
                }
#pragma unroll
            for (int mi = 0; mi < 2; mi++)
#pragma unroll
                for (int nj = 0; nj < 4; nj++) {
                    mma16816(acc[mi][2 * nj],     ah[mi], &blo[nj][0]);
                    mma16816(acc[mi][2 * nj + 1], ah[mi], &blo[nj][2]);
                }
        }
        __syncthreads();
    }

    // ---- epilogue: frags -> smem[u][o] (pad 132) -> bufB[(b*1024+u)*32+l]*512+o ----
    float* sep = (float*)smem;
    const int group = lane >> 2, tid4 = lane & 3;
#pragma unroll
    for (int mi = 0; mi < 2; mi++) {
        const int oo = warp_m * 32 + mi * 16 + group;
#pragma unroll
        for (int nj = 0; nj < 8; nj++) {
            const int uu = warp_n * 64 + nj * 8 + tid4 * 2;
            sep[(size_t)uu * EPAD + oo]           = acc[mi][nj][0];
            sep[(size_t)(uu + 1) * EPAD + oo]     = acc[mi][nj][1];
            sep[(size_t)uu * EPAD + oo + 8]       = acc[mi][nj][2];
            sep[(size_t)(uu + 1) * EPAD + oo + 8] = acc[mi][nj][3];
        }
    }
    __syncthreads();
    for (int r = wid; r < 128; r += 8) {
        float4 v = *(const float4*)&sep[(size_t)r * EPAD + lane * 4];
        *(float4*)(g_bufB + (((size_t)(bIdx * 1024 + u0 + r)) * 32 + lIdx) * 512
                          + o0 + lane * 4) = v;
    }
}

// ---------------- 3) attention: head-pair (h, h+4) packed in f32x2 ----------------
// kv2[c][i] float2 = (val_h, val_h+4); rows: c 0..15 q, 16..31 k, 32..63 v.
#define KV2S 34                                   // float2 row stride (272B, 16B-aligned)
#define ATTN_SMEM (16128 + 4 * 64 * KV2S * 8)     // rel_s + 4 warps * kv2 = 85760B

__global__ __launch_bounds__(128) void k_attn(const float* __restrict__ rel) {
    extern __shared__ __align__(16) float dsm[];
    float* rel_s = dsm;                           // [64*63]
    const int m = blockIdx.x;
    const int warp = threadIdx.x >> 5, lane = threadIdx.x & 31; // lane = i

    for (int t = threadIdx.x; t < 4032; t += 128) rel_s[t] = rel[t];
    __syncthreads();

    float2* kv2 = (float2*)(dsm + 4032) + (size_t)warp * 64 * KV2S;
    const int o1 = warp * 64, o2 = o1 + 256;      // heads warp, warp+4
    const float* base = g_bufB + (size_t)m * 16384;

    // stage both heads, transposed [c][i]
#pragma unroll 4
    for (int l = 0; l < 32; l++) {
        const float* bp = base + l * 512;
        float a0 = bp[o1 + lane],      a1 = bp[o2 + lane];
        float b0 = bp[o1 + 32 + lane], b1 = bp[o2 + 32 + lane];
        kv2[lane * KV2S + l]        = make_float2(a0, a1);
        kv2[(32 + lane) * KV2S + l] = make_float2(b0, b1);
    }
    __syncwarp();

    uint64_t sim2[32];
#pragma unroll
    for (int j = 0; j < 32; j++) sim2[j] = 0ull;

    for (int c = 0; c < 16; c++) {
        float2 qf = kv2[c * KV2S + lane];
        float2 kf = kv2[(16 + c) * KV2S + lane];
        const uint64_t qc2 = pk(qf.x, qf.y), kc2 = pk(kf.x, kf.y);
        const float4* rowk = (const float4*)(kv2 + (16 + c) * KV2S);
#pragma unroll
        for (int p = 0; p < 16; p++) {            // qk (broadcast, pre-packed pairs)
            float4 kk = rowk[p];
            fma2(sim2[2 * p],     qc2, pk(kk.x, kk.y));
            fma2(sim2[2 * p + 1], qc2, pk(kk.z, kk.w));
        }
        const float* rq = rel_s + c * 63 + lane;
        const float* rk = rel_s + (16 + c) * 63 + lane;
#pragma unroll
        for (int j = 0; j < 32; j++) {            // qr + kr (rel shared by both heads)
            float r1 = rq[j], r2 = rk[j];
            fma2(sim2[j], qc2, pk(r1, r1));
            fma2(sim2[j], kc2, pk(r2, r2));
        }
    }

    // softmax per head component (scale folded into final store)
    float mx1, mx2;
    upk(sim2[0], mx1, mx2);
#pragma unroll
    for (int j = 1; j < 32; j++) {
        float v1, v2; upk(sim2[j], v1, v2);
        mx1 = fmaxf(mx1, v1); mx2 = fmaxf(mx2, v2);
    }
    float s1 = 0.f, s2 = 0.f;
#pragma unroll
    for (int j = 0; j < 32; j++) {
        float v1, v2; upk(sim2[j], v1, v2);
        float e1 = __expf(v1 - mx1), e2 = __expf(v2 - mx2);
        s1 += e1; s2 += e2;
        sim2[j] = pk(e1, e2);
    }
    const float inv1 = 1.f / s1, inv2 = 1.f / s2;

    float* out1 = g_bufA + ((size_t)m * 512 + o1) * 32 + lane;
    float* out2 = g_bufA + ((size_t)m * 512 + o2) * 32 + lane;
#pragma unroll 2
    for (int c = 0; c < 32; c++) {
        const float4* rowv = (const float4*)(kv2 + (32 + c) * KV2S);
        uint64_t a2 = 0ull;
#pragma unroll
        for (int p = 0; p < 16; p++) {
            float4 vv = rowv[p];
            fma2(a2, sim2[2 * p],     pk(vv.x, vv.y));
            fma2(a2, sim2[2 * p + 1], pk(vv.z, vv.w));
        }
        const float* rv = rel_s + (32 + c) * 63 + lane;
        uint64_t e2 = 0ull;
#pragma unroll
        for (int j = 0; j < 32; j++) {
            float r = rv[j];
            fma2(e2, sim2[j], pk(r, r));
        }
        float alo, ahi, elo, ehi;
        upk(a2, alo, ahi); upk(e2, elo, ehi);
        out1[(2 * c) * 32]     = alo * inv1;
        out1[(2 * c + 1) * 32] = elo * inv1;
        out2[(2 * c) * 32]     = ahi * inv2;
        out2[(2 * c + 1) * 32] = ehi * inv2;
    }
}

// ---------------- 4) BN partial stats ---------------------------------------------
__global__ __launch_bounds__(256) void k_stats1() {
    const int ch = blockIdx.x, seg = blockIdx.y;
    const int w = threadIdx.x >> 5, lane = threadIdx.x & 31;
    float s = 0.f, q = 0.f;
    const int m0 = seg * 512;
    for (int t = 0; t < 64; t++) {
        const int m = m0 + w + t * 8;
        const float v = g_bufA[((size_t)m * 512 + ch) * 32 + lane];
        s += v; q = fmaf(v, v, q);
    }
#pragma unroll
    for (int o = 16; o; o >>= 1) {
        s += __shfl_down_sync(0xffffffffu, s, o);
        q += __shfl_down_sync(0xffffffffu, q, o);
    }
    __shared__ float ss[8], qs[8];
    if (lane == 0) { ss[w] = s; qs[w] = q; }
    __syncthreads();
    if (threadIdx.x == 0) {
        float S = 0.f, Q = 0.f;
        for (int t = 0; t < 8; t++) { S += ss[t]; Q += qs[t]; }
        g_part[ch * 8 + seg] = make_float2(S, Q);
    }
}

// ---------------- 5) finalize stats ------------------------------------------------
__global__ void k_stats2(const float* __restrict__ gamma, const float* __restrict__ beta) {
    const int ch = blockIdx.x * 32 + threadIdx.x;
    double s = 0.0, q = 0.0;
    for (int t = 0; t < 8; t++) { float2 p = g_part[ch * 8 + t]; s += p.x; q += p.y; }
    const double N = 131072.0;
    const double mean = s / N;
    const double var = q / N - mean * mean;
    const float sc = (float)((double)gamma[ch] * rsqrt(var + 1e-5));
    g_stats[ch] = make_float2(sc, (float)((double)beta[ch] - mean * (double)sc));
}

// ---------------- 6) normalize + pair-sum + transpose out -------------------------
__global__ __launch_bounds__(256) void k_out(float* __restrict__ out) {
    __shared__ float tile[32][33];
    const int u0 = blockIdx.x * 32, c = blockIdx.y, b = blockIdx.z;
    const int tx = threadIdx.x & 31, ty = threadIdx.x >> 5;
    const float2 p0 = g_stats[2 * c], p1 = g_stats[2 * c + 1];
    const float* base = g_bufA + ((size_t)(b * 1024 + u0) * 512 + 2 * c) * 32;
#pragma unroll
    for (int r = 0; r < 4; r++) {
        const int uu = ty + r * 8;
        const float* pp = base + (size_t)uu * 16384;
        tile[uu][tx] = fmaf(pp[tx], p0.x, p0.y) + fmaf(pp[32 + tx], p1.x, p1.y);
    }
    __syncthreads();
    float* op = out + (size_t)(b * 256 + c) * 32768 + u0;
#pragma unroll
    for (int r = 0; r < 4; r++) {
        const int l = ty + r * 8;
        op[(size_t)l * 1024 + tx] = tile[tx][l];
    }
}

extern "C" void kernel_launch(void* const* d_in, const int* in_sizes, int n_in,
                              void* d_out, int out_size) {
    const float* x     = (const float*)d_in[0];
    const float* Wq    = (const float*)d_in[1];
    const float* rel   = (const float*)d_in[2];
    const float* gamma = (const float*)d_in[3];
    const float* beta  = (const float*)d_in[4];
    float* out = (float*)d_out;

    cudaFuncSetAttribute(k_gemm_mma, cudaFuncAttributeMaxDynamicSharedMemorySize, SM_TOTAL);
    cudaFuncSetAttribute(k_attn, cudaFuncAttributeMaxDynamicSharedMemorySize, ATTN_SMEM);

    k_prep_w  <<<512, 256>>>(Wq);
    k_prep_x  <<<dim3(32, 8, 128), 256>>>(x);
    k_gemm_mma<<<dim3(8, 4, 128), 256, SM_TOTAL>>>();
    k_attn    <<<4096, 128, ATTN_SMEM>>>(rel);
    k_stats1  <<<dim3(512, 8), 256>>>();
    k_stats2  <<<16, 32>>>(gamma, beta);
    k_out     <<<dim3(32, 256, 4), 256>>>(out);
}

// round 16
// speedup vs baseline: 1.8164x; 1.1141x over previous
#include <cuda_runtime.h>
#include <cuda_bf16.h>
#include <math.h>
#include <stdint.h>

// x:(4,256,32,32,32) f32 | qkv_weight:(512,256) | relative:(64,63) | gamma,beta:(512)
// m-order: m = b*1024 + w*32 + t (u = w*32+t). Legal permutation of reference n.
// GEMM: mma.sync bf16 split precision (Wh*Xh + Wl*Xh + Wh*Xl), cp.async double-buffered,
//       epilogue writes bufB[m][l][o] via smem transpose (EPAD=132, 16B-aligned rows).
// Attention: head-pair f32x2 packing; kv2 TIME-MULTIPLEXED (q+k, then v in same 32 rows)
//       -> smem/block 50.9KB -> 4 CTAs/SM (R15 ncu: occ 12.3% was the binder).

__device__ float  g_bufA[67108864];  // st: (m*512+ch)*32+i   (attention output)
__device__ float  g_bufB[67108864];  // qkv: ((m*32)+l)*512+o  = [m][l][o]
__device__ __nv_bfloat16 g_xh[33554432]; // xT hi: (bl*1024+u)*256 + c
__device__ __nv_bfloat16 g_xl[33554432]; // xT lo
__device__ __nv_bfloat16 g_wh[131072];   // W hi: [o][c]
__device__ __nv_bfloat16 g_wl[131072];   // W lo
__device__ float2 g_part[512 * 8];
__device__ float2 g_stats[512];

// ---------------- helpers ---------------------------------------------------------
__device__ __forceinline__ uint32_t smem_u32(const void* p) {
    uint32_t a;
    asm("{ .reg .u64 t; cvta.to.shared.u64 t, %1; cvt.u32.u64 %0, t; }" : "=r"(a) : "l"(p));
    return a;
}
__device__ __forceinline__ void ldm_x4(uint32_t* r, uint32_t addr) {
    asm volatile("ldmatrix.sync.aligned.m8n8.x4.shared.b16 {%0,%1,%2,%3}, [%4];"
        : "=r"(r[0]), "=r"(r[1]), "=r"(r[2]), "=r"(r[3]) : "r"(addr));
}
__device__ __forceinline__ void mma16816(float* d, const uint32_t* a, const uint32_t* b) {
    asm volatile("mma.sync.aligned.m16n8k16.row.col.f32.bf16.bf16.f32 "
        "{%0,%1,%2,%3}, {%4,%5,%6,%7}, {%8,%9}, {%0,%1,%2,%3};"
        : "+f"(d[0]), "+f"(d[1]), "+f"(d[2]), "+f"(d[3])
        : "r"(a[0]), "r"(a[1]), "r"(a[2]), "r"(a[3]), "r"(b[0]), "r"(b[1]));
}
__device__ __forceinline__ void cpa16(uint32_t dst, const void* src) {
    asm volatile("cp.async.ca.shared.global [%0], [%1], 16;" :: "r"(dst), "l"(src));
}
#define CPA_COMMIT() asm volatile("cp.async.commit_group;" ::: "memory")
#define CPA_WAIT(n)  asm volatile("cp.async.wait_group %0;" :: "n"(n) : "memory")

__device__ __forceinline__ void fma2(uint64_t& d, uint64_t a, uint64_t b) {
    asm("fma.rn.f32x2 %0, %1, %2, %0;" : "+l"(d) : "l"(a), "l"(b));
}
__device__ __forceinline__ uint64_t pk(float lo, float hi) {
    uint64_t r; asm("mov.b64 %0, {%1,%2};" : "=l"(r) : "f"(lo), "f"(hi)); return r;
}
__device__ __forceinline__ void upk(uint64_t v, float& lo, float& hi) {
    asm("mov.b64 {%0,%1}, %2;" : "=f"(lo), "=f"(hi) : "l"(v));
}
#define SW128(o) ((o) ^ ((((uint32_t)(o)) >> 3) & 0x70))

// ---------------- 0a) W -> bf16 hi/lo ---------------------------------------------
__global__ void k_prep_w(const float* __restrict__ W) {
    int i = blockIdx.x * 256 + threadIdx.x;
    if (i < 131072) {
        float f = W[i];
        __nv_bfloat16 h = __float2bfloat16(f);
        g_wh[i] = h;
        g_wl[i] = __float2bfloat16(f - __bfloat162float(h));
    }
}

// ---------------- 0b) x -> transposed bf16 hi/lo: [bl][u][c] ----------------------
__global__ __launch_bounds__(256) void k_prep_x(const float* __restrict__ x) {
    __shared__ float tile[32][33];
    const int u0 = blockIdx.x * 32, c0 = blockIdx.y * 32, bl = blockIdx.z;
    const int b = bl >> 5, l = bl & 31;
    const float* src = x + ((size_t)(b * 256 + c0) * 32 + l) * 1024 + u0;
    for (int idx = threadIdx.x; idx < 1024; idx += 256) {
        int cc = idx >> 5, uu = idx & 31;
        tile[cc][uu] = src[(size_t)cc * 32768 + uu];
    }
    __syncthreads();
    for (int idx = threadIdx.x; idx < 512; idx += 256) {
        int uu = idx >> 4, cp = idx & 15;
        float f0 = tile[2 * cp][uu], f1 = tile[2 * cp + 1][uu];
        __nv_bfloat16 h0 = __float2bfloat16(f0), h1 = __float2bfloat16(f1);
        __nv_bfloat16 e0 = __float2bfloat16(f0 - __bfloat162float(h0));
        __nv_bfloat16 e1 = __float2bfloat16(f1 - __bfloat162float(h1));
        size_t off = ((size_t)bl * 1024 + u0 + uu) * 256 + c0 + 2 * cp;
        __nv_bfloat162 hh; hh.x = h0; hh.y = h1;
        __nv_bfloat162 ll; ll.x = e0; ll.y = e1;
        *(__nv_bfloat162*)(g_xh + off) = hh;
        *(__nv_bfloat162*)(g_xl + off) = ll;
    }
}

// ---------------- 1) QKV GEMM via mma.sync bf16, epilogue -> bufB[m][l][o] --------
#define SA_H 0
#define SA_L 16384
#define SB_H 32768
#define SB_L 49152
#define STAGE_SZ 65536
#define SM_TOTAL 131072
#define EPAD 132

__global__ __launch_bounds__(256) void k_gemm_mma() {
    extern __shared__ __align__(1024) char smem[];
    const uint32_t sb = smem_u32(smem);
    const int tid = threadIdx.x, wid = tid >> 5, lane = tid & 31;
    const int bl = blockIdx.z, bIdx = bl >> 5, lIdx = bl & 31;
    const int u0 = blockIdx.x * 128, o0 = blockIdx.y * 128;
    const int warp_m = wid & 3, warp_n = wid >> 2;  // 4 x 2 warps

    float acc[2][8][4];
#pragma unroll
    for (int mi = 0; mi < 2; mi++)
#pragma unroll
        for (int nj = 0; nj < 8; nj++)
#pragma unroll
            for (int r = 0; r < 4; r++) acc[mi][nj][r] = 0.f;

    const uint32_t a_row = warp_m * 32 + (lane & 15);
    const uint32_t a_cb  = (lane >> 4) << 4;
    const uint32_t b_cb  = ((lane >> 3) & 1) << 4;
    const uint32_t b_rbase = warp_n * 64 + ((lane >> 4) << 3) + (lane & 7);

    auto fill = [&](int kc, int stage) {
        const int k0 = kc * 64;
        const uint32_t st = sb + stage * STAGE_SZ;
#pragma unroll
        for (int it = 0; it < 4; it++) {
            const int id = tid + it * 256;
            const int row = id >> 3, seg = id & 7;
            const uint32_t so = SW128(row * 128 + seg * 16);
            const size_t aoff = (size_t)(o0 + row) * 256 + k0 + seg * 8;
            const size_t boff = ((size_t)bl * 1024 + u0 + row) * 256 + k0 + seg * 8;
            cpa16(st + SA_H + so, g_wh + aoff);
            cpa16(st + SA_L + so, g_wl + aoff);
            cpa16(st + SB_H + so, g_xh + boff);
            cpa16(st + SB_L + so, g_xl + boff);
        }
    };

    fill(0, 0);
    CPA_COMMIT();

    for (int kc = 0; kc < 4; kc++) {
        if (kc < 3) { fill(kc + 1, (kc + 1) & 1); CPA_COMMIT(); }
        if (kc < 3) { CPA_WAIT(1); } else { CPA_WAIT(0); }
        __syncthreads();
        const uint32_t st = sb + (kc & 1) * STAGE_SZ;

#pragma unroll
        for (int ks = 0; ks < 4; ks++) {
            const uint32_t kb = ks * 32;
            uint32_t ah[2][4], al[2][4];
#pragma unroll
            for (int mi = 0; mi < 2; mi++) {
                const uint32_t off = SW128((a_row + mi * 16) * 128 + kb + a_cb);
                ldm_x4(ah[mi], st + SA_H + off);
                ldm_x4(al[mi], st + SA_L + off);
            }
            uint32_t bh[4][4], blo[4][4];
#pragma unroll
            for (int nj = 0; nj < 4; nj++) {
                const uint32_t off = SW128((b_rbase + nj * 16) * 128 + kb + b_cb);
                ldm_x4(bh[nj], st + SB_H + off);
                ldm_x4(blo[nj], st + SB_L + off);
            }
#pragma unroll
            for (int mi = 0; mi < 2; mi++)
#pragma unroll
                for (int nj = 0; nj < 4; nj++) {
                    mma16816(acc[mi][2 * nj],     ah[mi], &bh[nj][0]);
                    mma16816(acc[mi][2 * nj + 1], ah[mi], &bh[nj][2]);
                }
#pragma unroll
            for (int mi = 0; mi < 2; mi++)
#pragma unroll
                for (int nj = 0; nj < 4; nj++) {
                    mma16816(acc[mi][2 * nj],     al[mi], &bh[nj][0]);
                    mma16816(acc[mi][2 * nj + 1], al[mi], &bh[nj][2]);
                }
#pragma unroll
            for (int mi = 0; mi < 2; mi++)
#pragma unroll
                for (int nj = 0; nj < 4; nj++) {
                    mma16816(acc[mi][2 * nj],     ah[mi], &blo[nj][0]);
                    mma16816(acc[mi][2 * nj + 1], ah[mi], &blo[nj][2]);
                }
        }
        __syncthreads();
    }

    // ---- epilogue: frags -> smem[u][o] (pad 132) -> bufB[(b*1024+u)*32+l]*512+o ----
    float* sep = (float*)smem;
    const int group = lane >> 2, tid4 = lane & 3;
#pragma unroll
    for (int mi = 0; mi < 2; mi++) {
        const int oo = warp_m * 32 + mi * 16 + group;
#pragma unroll
        for (int nj = 0; nj < 8; nj++) {
            const int uu = warp_n * 64 + nj * 8 + tid4 * 2;
            sep[(size_t)uu * EPAD + oo]           = acc[mi][nj][0];
            sep[(size_t)(uu + 1) * EPAD + oo]     = acc[mi][nj][1];
            sep[(size_t)uu * EPAD + oo + 8]       = acc[mi][nj][2];
            sep[(size_t)(uu + 1) * EPAD + oo + 8] = acc[mi][nj][3];
        }
    }
    __syncthreads();
    for (int r = wid; r < 128; r += 8) {
        float4 v = *(const float4*)&sep[(size_t)r * EPAD + lane * 4];
        *(float4*)(g_bufB + (((size_t)(bIdx * 1024 + u0 + r)) * 32 + lIdx) * 512
                          + o0 + lane * 4) = v;
    }
}

// ---------------- 3) attention: head-pair f32x2, kv2 time-multiplexed -------------
// Phase 1: kv2 rows 0..15 = q, 16..31 = k -> logits+softmax.
// Phase 2: same rows overwritten with v (32 rows) -> sv/sve.
#define KV2S 34                                   // float2 row stride (272B, 16B-aligned)
#define ATTN_SMEM (16128 + 4 * 32 * KV2S * 8)     // rel_s + 4 warps * kv2[32][34] = 50944B

__global__ __launch_bounds__(128) void k_attn(const float* __restrict__ rel) {
    extern __shared__ __align__(16) float dsm[];
    float* rel_s = dsm;                           // [64*63]
    const int m = blockIdx.x;
    const int warp = threadIdx.x >> 5, lane = threadIdx.x & 31; // lane = i

    for (int t = threadIdx.x; t < 4032; t += 128) rel_s[t] = rel[t];
    __syncthreads();

    float2* kv2 = (float2*)(dsm + 4032) + (size_t)warp * 32 * KV2S;
    const int o1 = warp * 64, o2 = o1 + 256;      // heads warp, warp+4
    const float* base = g_bufB + (size_t)m * 16384;

    // ---- phase 1: stage q+k (channels 0..31), transposed [c][i] ----
#pragma unroll 4
    for (int l = 0; l < 32; l++) {
        const float* bp = base + l * 512;
        kv2[lane * KV2S + l] = make_float2(bp[o1 + lane], bp[o2 + lane]);
    }
    __syncwarp();

    uint64_t sim2[32];
#pragma unroll
    for (int j = 0; j < 32; j++) sim2[j] = 0ull;

    for (int c = 0; c < 16; c++) {
        float2 qf = kv2[c * KV2S + lane];
        float2 kf = kv2[(16 + c) * KV2S + lane];
        const uint64_t qc2 = pk(qf.x, qf.y), kc2 = pk(kf.x, kf.y);
        const float4* rowk = (const float4*)(kv2 + (16 + c) * KV2S);
#pragma unroll
        for (int p = 0; p < 16; p++) {            // qk (broadcast, pre-packed pairs)
            float4 kk = rowk[p];
            fma2(sim2[2 * p],     qc2, pk(kk.x, kk.y));
            fma2(sim2[2 * p + 1], qc2, pk(kk.z, kk.w));
        }
        const float* rq = rel_s + c * 63 + lane;
        const float* rk = rel_s + (16 + c) * 63 + lane;
#pragma unroll
        for (int j = 0; j < 32; j++) {            // qr + kr (rel shared by both heads)
            float r1 = rq[j], r2 = rk[j];
            fma2(sim2[j], qc2, pk(r1, r1));
            fma2(sim2[j], kc2, pk(r2, r2));
        }
    }

    // softmax per head component (scale folded into final store)
    float mx1, mx2;
    upk(sim2[0], mx1, mx2);
#pragma unroll
    for (int j = 1; j < 32; j++) {
        float v1, v2; upk(sim2[j], v1, v2);
        mx1 = fmaxf(mx1, v1); mx2 = fmaxf(mx2, v2);
    }
    float s1 = 0.f, s2 = 0.f;
#pragma unroll
    for (int j = 0; j < 32; j++) {
        float v1, v2; upk(sim2[j], v1, v2);
        float e1 = __expf(v1 - mx1), e2 = __expf(v2 - mx2);
        s1 += e1; s2 += e2;
        sim2[j] = pk(e1, e2);
    }
    const float inv1 = 1.f / s1, inv2 = 1.f / s2;

    // ---- phase 2: overwrite kv2 with v (channels 32..63) ----
    __syncwarp();
#pragma unroll 4
    for (int l = 0; l < 32; l++) {
        const float* bp = base + l * 512;
        kv2[lane * KV2S + l] = make_float2(bp[o1 + 32 + lane], bp[o2 + 32 + lane]);
    }
    __syncwarp();

    float* out1 = g_bufA + ((size_t)m * 512 + o1) * 32 + lane;
    float* out2 = g_bufA + ((size_t)m * 512 + o2) * 32 + lane;
#pragma unroll 2
    for (int c = 0; c < 32; c++) {
        const float4* rowv = (const float4*)(kv2 + c * KV2S);
        uint64_t a2 = 0ull;
#pragma unroll
        for (int p = 0; p < 16; p++) {
            float4 vv = rowv[p];
            fma2(a2, sim2[2 * p],     pk(vv.x, vv.y));
            fma2(a2, sim2[2 * p + 1], pk(vv.z, vv.w));
        }
        const float* rv = rel_s + (32 + c) * 63 + lane;
        uint64_t e2 = 0ull;
#pragma unroll
        for (int j = 0; j < 32; j++) {
            float r = rv[j];
            fma2(e2, sim2[j], pk(r, r));
        }
        float alo, ahi, elo, ehi;
        upk(a2, alo, ahi); upk(e2, elo, ehi);
        out1[(2 * c) * 32]     = alo * inv1;
        out1[(2 * c + 1) * 32] = elo * inv1;
        out2[(2 * c) * 32]     = ahi * inv2;
        out2[(2 * c + 1) * 32] = ehi * inv2;
    }
}

// ---------------- 4) BN partial stats ---------------------------------------------
__global__ __launch_bounds__(256) void k_stats1() {
    const int ch = blockIdx.x, seg = blockIdx.y;
    const int w = threadIdx.x >> 5, lane = threadIdx.x & 31;
    float s = 0.f, q = 0.f;
    const int m0 = seg * 512;
    for (int t = 0; t < 64; t++) {
        const int m = m0 + w + t * 8;
        const float v = g_bufA[((size_t)m * 512 + ch) * 32 + lane];
        s += v; q = fmaf(v, v, q);
    }
#pragma unroll
    for (int o = 16; o; o >>= 1) {
        s += __shfl_down_sync(0xffffffffu, s, o);
        q += __shfl_down_sync(0xffffffffu, q, o);
    }
    __shared__ float ss[8], qs[8];
    if (lane == 0) { ss[w] = s; qs[w] = q; }
    __syncthreads();
    if (threadIdx.x == 0) {
        float S = 0.f, Q = 0.f;
        for (int t = 0; t < 8; t++) { S += ss[t]; Q += qs[t]; }
        g_part[ch * 8 + seg] = make_float2(S, Q);
    }
}

// ---------------- 5) finalize stats ------------------------------------------------
__global__ void k_stats2(const float* __restrict__ gamma, const float* __restrict__ beta) {
    const int ch = blockIdx.x * 32 + threadIdx.x;
    double s = 0.0, q = 0.0;
    for (int t = 0; t < 8; t++) { float2 p = g_part[ch * 8 + t]; s += p.x; q += p.y; }
    const double N = 131072.0;
    const double mean = s / N;
    const double var = q / N - mean * mean;
    const float sc = (float)((double)gamma[ch] * rsqrt(var + 1e-5));
    g_stats[ch] = make_float2(sc, (float)((double)beta[ch] - mean * (double)sc));
}

// ---------------- 6) normalize + pair-sum + transpose out -------------------------
__global__ __launch_bounds__(256) void k_out(float* __restrict__ out) {
    __shared__ float tile[32][33];
    const int u0 = blockIdx.x * 32, c = blockIdx.y, b = blockIdx.z;
    const int tx = threadIdx.x & 31, ty = threadIdx.x >> 5;
    const float2 p0 = g_stats[2 * c], p1 = g_stats[2 * c + 1];
    const float* base = g_bufA + ((size_t)(b * 1024 + u0) * 512 + 2 * c) * 32;
#pragma unroll
    for (int r = 0; r < 4; r++) {
        const int uu = ty + r * 8;
        const float* pp = base + (size_t)uu * 16384;
        tile[uu][tx] = fmaf(pp[tx], p0.x, p0.y) + fmaf(pp[32 + tx], p1.x, p1.y);
    }
    __syncthreads();
    float* op = out + (size_t)(b * 256 + c) * 32768 + u0;
#pragma unroll
    for (int r = 0; r < 4; r++) {
        const int l = ty + r * 8;
        op[(size_t)l * 1024 + tx] = tile[tx][l];
    }
}

extern "C" void kernel_launch(void* const* d_in, const int* in_sizes, int n_in,
                              void* d_out, int out_size) {
    const float* x     = (const float*)d_in[0];
    const float* Wq    = (const float*)d_in[1];
    const float* rel   = (const float*)d_in[2];
    const float* gamma = (const float*)d_in[3];
    const float* beta  = (const float*)d_in[4];
    float* out = (float*)d_out;

    cudaFuncSetAttribute(k_gemm_mma, cudaFuncAttributeMaxDynamicSharedMemorySize, SM_TOTAL);
    cudaFuncSetAttribute(k_attn, cudaFuncAttributeMaxDynamicSharedMemorySize, ATTN_SMEM);

    k_prep_w  <<<512, 256>>>(Wq);
    k_prep_x  <<<dim3(32, 8, 128), 256>>>(x);
    k_gemm_mma<<<dim3(8, 4, 128), 256, SM_TOTAL>>>();
    k_attn    <<<4096, 128, ATTN_SMEM>>>(rel);
    k_stats1  <<<dim3(512, 8), 256>>>();
    k_stats2  <<<16, 32>>>(gamma, beta);
    k_out     <<<dim3(32, 256, 4), 256>>>(out);
}

// round 17
// speedup vs baseline: 1.8199x; 1.0019x over previous
#include <cuda_runtime.h>
#include <cuda_bf16.h>
#include <math.h>
#include <stdint.h>

// x:(4,256,32,32,32) f32 | qkv_weight:(512,256) | relative:(64,63) | gamma,beta:(512)
// m-order: m = b*1024 + w*32 + t (u = w*32+t). Legal permutation of reference n.
// GEMM: mma.sync bf16 split precision (Wh*Xh + Wl*Xh + Wh*Xl), cp.async double-buffered.
//       R17: tile 128(o)x64(u), stage 48KB, 2 stages = 96KB/CTA -> 2 CTAs/SM
//       (launch_bounds(256,2)); prologue/epilogue now overlap across CTAs.
// Attention: head-pair f32x2, kv2 time-multiplexed (unchanged from R16; crossbar-saturated).

__device__ float  g_bufA[67108864];  // st: (m*512+ch)*32+i   (attention output)
__device__ float  g_bufB[67108864];  // qkv: ((m*32)+l)*512+o  = [m][l][o]
__device__ __nv_bfloat16 g_xh[33554432]; // xT hi: (bl*1024+u)*256 + c
__device__ __nv_bfloat16 g_xl[33554432]; // xT lo
__device__ __nv_bfloat16 g_wh[131072];   // W hi: [o][c]
__device__ __nv_bfloat16 g_wl[131072];   // W lo
__device__ float2 g_part[512 * 8];
__device__ float2 g_stats[512];

// ---------------- helpers ---------------------------------------------------------
__device__ __forceinline__ uint32_t smem_u32(const void* p) {
    uint32_t a;
    asm("{ .reg .u64 t; cvta.to.shared.u64 t, %1; cvt.u32.u64 %0, t; }" : "=r"(a) : "l"(p));
    return a;
}
__device__ __forceinline__ void ldm_x4(uint32_t* r, uint32_t addr) {
    asm volatile("ldmatrix.sync.aligned.m8n8.x4.shared.b16 {%0,%1,%2,%3}, [%4];"
        : "=r"(r[0]), "=r"(r[1]), "=r"(r[2]), "=r"(r[3]) : "r"(addr));
}
__device__ __forceinline__ void mma16816(float* d, const uint32_t* a, const uint32_t* b) {
    asm volatile("mma.sync.aligned.m16n8k16.row.col.f32.bf16.bf16.f32 "
        "{%0,%1,%2,%3}, {%4,%5,%6,%7}, {%8,%9}, {%0,%1,%2,%3};"
        : "+f"(d[0]), "+f"(d[1]), "+f"(d[2]), "+f"(d[3])
        : "r"(a[0]), "r"(a[1]), "r"(a[2]), "r"(a[3]), "r"(b[0]), "r"(b[1]));
}
__device__ __forceinline__ void cpa16(uint32_t dst, const void* src) {
    asm volatile("cp.async.ca.shared.global [%0], [%1], 16;" :: "r"(dst), "l"(src));
}
#define CPA_COMMIT() asm volatile("cp.async.commit_group;" ::: "memory")
#define CPA_WAIT(n)  asm volatile("cp.async.wait_group %0;" :: "n"(n) : "memory")

__device__ __forceinline__ void fma2(uint64_t& d, uint64_t a, uint64_t b) {
    asm("fma.rn.f32x2 %0, %1, %2, %0;" : "+l"(d) : "l"(a), "l"(b));
}
__device__ __forceinline__ uint64_t pk(float lo, float hi) {
    uint64_t r; asm("mov.b64 %0, {%1,%2};" : "=l"(r) : "f"(lo), "f"(hi)); return r;
}
__device__ __forceinline__ void upk(uint64_t v, float& lo, float& hi) {
    asm("mov.b64 {%0,%1}, %2;" : "=f"(lo), "=f"(hi) : "l"(v));
}
#define SW128(o) ((o) ^ ((((uint32_t)(o)) >> 3) & 0x70))

// ---------------- 0a) W -> bf16 hi/lo ---------------------------------------------
__global__ void k_prep_w(const float* __restrict__ W) {
    int i = blockIdx.x * 256 + threadIdx.x;
    if (i < 131072) {
        float f = W[i];
        __nv_bfloat16 h = __float2bfloat16(f);
        g_wh[i] = h;
        g_wl[i] = __float2bfloat16(f - __bfloat162float(h));
    }
}

// ---------------- 0b) x -> transposed bf16 hi/lo: [bl][u][c] ----------------------
__global__ __launch_bounds__(256) void k_prep_x(const float* __restrict__ x) {
    __shared__ float tile[32][33];
    const int u0 = blockIdx.x * 32, c0 = blockIdx.y * 32, bl = blockIdx.z;
    const int b = bl >> 5, l = bl & 31;
    const float* src = x + ((size_t)(b * 256 + c0) * 32 + l) * 1024 + u0;
    for (int idx = threadIdx.x; idx < 1024; idx += 256) {
        int cc = idx >> 5, uu = idx & 31;
        tile[cc][uu] = src[(size_t)cc * 32768 + uu];
    }
    __syncthreads();
    for (int idx = threadIdx.x; idx < 512; idx += 256) {
        int uu = idx >> 4, cp = idx & 15;
        float f0 = tile[2 * cp][uu], f1 = tile[2 * cp + 1][uu];
        __nv_bfloat16 h0 = __float2bfloat16(f0), h1 = __float2bfloat16(f1);
        __nv_bfloat16 e0 = __float2bfloat16(f0 - __bfloat162float(h0));
        __nv_bfloat16 e1 = __float2bfloat16(f1 - __bfloat162float(h1));
        size_t off = ((size_t)bl * 1024 + u0 + uu) * 256 + c0 + 2 * cp;
        __nv_bfloat162 hh; hh.x = h0; hh.y = h1;
        __nv_bfloat162 ll; ll.x = e0; ll.y = e1;
        *(__nv_bfloat162*)(g_xh + off) = hh;
        *(__nv_bfloat162*)(g_xl + off) = ll;
    }
}

// ---------------- 1) QKV GEMM via mma.sync bf16, 128x64 tile, 2 CTAs/SM -----------
#define SA_H 0
#define SA_L 16384
#define SB_H 32768
#define SB_L 40960
#define STAGE_SZ 49152
#define SM_TOTAL 98304
#define EPAD 132

__global__ __launch_bounds__(256, 2) void k_gemm_mma() {
    extern __shared__ __align__(1024) char smem[];
    const uint32_t sb = smem_u32(smem);
    const int tid = threadIdx.x, wid = tid >> 5, lane = tid & 31;
    const int bl = blockIdx.z, bIdx = bl >> 5, lIdx = bl & 31;
    const int u0 = blockIdx.x * 64, o0 = blockIdx.y * 128;
    const int warp_m = wid & 3, warp_n = wid >> 2;  // 4 x 2 warps, warp tile 32x32

    float acc[2][4][4];
#pragma unroll
    for (int mi = 0; mi < 2; mi++)
#pragma unroll
        for (int nj = 0; nj < 4; nj++)
#pragma unroll
            for (int r = 0; r < 4; r++) acc[mi][nj][r] = 0.f;

    const uint32_t a_row = warp_m * 32 + (lane & 15);
    const uint32_t a_cb  = (lane >> 4) << 4;
    const uint32_t b_cb  = ((lane >> 3) & 1) << 4;
    const uint32_t b_rbase = warp_n * 32 + ((lane >> 4) << 3) + (lane & 7);

    auto fill = [&](int kc, int stage) {
        const int k0 = kc * 64;
        const uint32_t st = sb + stage * STAGE_SZ;
#pragma unroll
        for (int it = 0; it < 4; it++) {                 // A: 128 rows x 8 segs
            const int id = tid + it * 256;
            const int row = id >> 3, seg = id & 7;
            const uint32_t so = SW128(row * 128 + seg * 16);
            const size_t aoff = (size_t)(o0 + row) * 256 + k0 + seg * 8;
            cpa16(st + SA_H + so, g_wh + aoff);
            cpa16(st + SA_L + so, g_wl + aoff);
        }
#pragma unroll
        for (int it = 0; it < 2; it++) {                 // B: 64 rows x 8 segs
            const int id = tid + it * 256;
            const int row = id >> 3, seg = id & 7;
            const uint32_t so = SW128(row * 128 + seg * 16);
            const size_t boff = ((size_t)bl * 1024 + u0 + row) * 256 + k0 + seg * 8;
            cpa16(st + SB_H + so, g_xh + boff);
            cpa16(st + SB_L + so, g_xl + boff);
        }
    };

    fill(0, 0);
    CPA_COMMIT();

    for (int kc = 0; kc < 4; kc++) {
        if (kc < 3) { fill(kc + 1, (kc + 1) & 1); CPA_COMMIT(); }
        if (kc < 3) { CPA_WAIT(1); } else { CPA_WAIT(0); }
        __syncthreads();
        const uint32_t st = sb + (kc & 1) * STAGE_SZ;

#pragma unroll
        for (int ks = 0; ks < 4; ks++) {
            const uint32_t kb = ks * 32;
            uint32_t ah[2][4], al[2][4];
#pragma unroll
            for (int mi = 0; mi < 2; mi++) {
                const uint32_t off = SW128((a_row + mi * 16) * 128 + kb + a_cb);
                ldm_x4(ah[mi], st + SA_H + off);
                ldm_x4(al[mi], st + SA_L + off);
            }
            uint32_t bh[2][4], blo[2][4];
#pragma unroll
            for (int nj = 0; nj < 2; nj++) {
                const uint32_t off = SW128((b_rbase + nj * 16) * 128 + kb + b_cb);
                ldm_x4(bh[nj], st + SB_H + off);
                ldm_x4(blo[nj], st + SB_L + off);
            }
#pragma unroll
            for (int mi = 0; mi < 2; mi++)
#pragma unroll
                for (int nj = 0; nj < 2; nj++) {
                    mma16816(acc[mi][2 * nj],     ah[mi], &bh[nj][0]);
                    mma16816(acc[mi][2 * nj + 1], ah[mi], &bh[nj][2]);
                }
#pragma unroll
            for (int mi = 0; mi < 2; mi++)
#pragma unroll
                for (int nj = 0; nj < 2; nj++) {
                    mma16816(acc[mi][2 * nj],     al[mi], &bh[nj][0]);
                    mma16816(acc[mi][2 * nj + 1], al[mi], &bh[nj][2]);
                }
#pragma unroll
            for (int mi = 0; mi < 2; mi++)
#pragma unroll
                for (int nj = 0; nj < 2; nj++) {
                    mma16816(acc[mi][2 * nj],     ah[mi], &blo[nj][0]);
                    mma16816(acc[mi][2 * nj + 1], ah[mi], &blo[nj][2]);
                }
        }
        __syncthreads();
    }

    // ---- epilogue: frags -> smem[u][o] (pad 132) -> bufB[(b*1024+u)*32+l]*512+o ----
    float* sep = (float*)smem;
    const int group = lane >> 2, tid4 = lane & 3;
#pragma unroll
    for (int mi = 0; mi < 2; mi++) {
        const int oo = warp_m * 32 + mi * 16 + group;
#pragma unroll
        for (int nj = 0; nj < 4; nj++) {
            const int uu = warp_n * 32 + nj * 8 + tid4 * 2;
            sep[(size_t)uu * EPAD + oo]           = acc[mi][nj][0];
            sep[(size_t)(uu + 1) * EPAD + oo]     = acc[mi][nj][1];
            sep[(size_t)uu * EPAD + oo + 8]       = acc[mi][nj][2];
            sep[(size_t)(uu + 1) * EPAD + oo + 8] = acc[mi][nj][3];
        }
    }
    __syncthreads();
    for (int r = wid; r < 64; r += 8) {
        float4 v = *(const float4*)&sep[(size_t)r * EPAD + lane * 4];
        *(float4*)(g_bufB + (((size_t)(bIdx * 1024 + u0 + r)) * 32 + lIdx) * 512
                          + o0 + lane * 4) = v;
    }
}

// ---------------- 3) attention: head-pair f32x2, kv2 time-multiplexed -------------
#define KV2S 34                                   // float2 row stride (272B, 16B-aligned)
#define ATTN_SMEM (16128 + 4 * 32 * KV2S * 8)     // rel_s + 4 warps * kv2[32][34] = 50944B

__global__ __launch_bounds__(128) void k_attn(const float* __restrict__ rel) {
    extern __shared__ __align__(16) float dsm[];
    float* rel_s = dsm;                           // [64*63]
    const int m = blockIdx.x;
    const int warp = threadIdx.x >> 5, lane = threadIdx.x & 31; // lane = i

    for (int t = threadIdx.x; t < 4032; t += 128) rel_s[t] = rel[t];
    __syncthreads();

    float2* kv2 = (float2*)(dsm + 4032) + (size_t)warp * 32 * KV2S;
    const int o1 = warp * 64, o2 = o1 + 256;      // heads warp, warp+4
    const float* base = g_bufB + (size_t)m * 16384;

    // ---- phase 1: stage q+k (channels 0..31), transposed [c][i] ----
#pragma unroll 4
    for (int l = 0; l < 32; l++) {
        const float* bp = base + l * 512;
        kv2[lane * KV2S + l] = make_float2(bp[o1 + lane], bp[o2 + lane]);
    }
    __syncwarp();

    uint64_t sim2[32];
#pragma unroll
    for (int j = 0; j < 32; j++) sim2[j] = 0ull;

    for (int c = 0; c < 16; c++) {
        float2 qf = kv2[c * KV2S + lane];
        float2 kf = kv2[(16 + c) * KV2S + lane];
        const uint64_t qc2 = pk(qf.x, qf.y), kc2 = pk(kf.x, kf.y);
        const float4* rowk = (const float4*)(kv2 + (16 + c) * KV2S);
#pragma unroll
        for (int p = 0; p < 16; p++) {            // qk (broadcast, pre-packed pairs)
            float4 kk = rowk[p];
            fma2(sim2[2 * p],     qc2, pk(kk.x, kk.y));
            fma2(sim2[2 * p + 1], qc2, pk(kk.z, kk.w));
        }
        const float* rq = rel_s + c * 63 + lane;
        const float* rk = rel_s + (16 + c) * 63 + lane;
#pragma unroll
        for (int j = 0; j < 32; j++) {            // qr + kr (rel shared by both heads)
            float r1 = rq[j], r2 = rk[j];
            fma2(sim2[j], qc2, pk(r1, r1));
            fma2(sim2[j], kc2, pk(r2, r2));
        }
    }

    // softmax per head component (scale folded into final store)
    float mx1, mx2;
    upk(sim2[0], mx1, mx2);
#pragma unroll
    for (int j = 1; j < 32; j++) {
        float v1, v2; upk(sim2[j], v1, v2);
        mx1 = fmaxf(mx1, v1); mx2 = fmaxf(mx2, v2);
    }
    float s1 = 0.f, s2 = 0.f;
#pragma unroll
    for (int j = 0; j < 32; j++) {
        float v1, v2; upk(sim2[j], v1, v2);
        float e1 = __expf(v1 - mx1), e2 = __expf(v2 - mx2);
        s1 += e1; s2 += e2;
        sim2[j] = pk(e1, e2);
    }
    const float inv1 = 1.f / s1, inv2 = 1.f / s2;

    // ---- phase 2: overwrite kv2 with v (channels 32..63) ----
    __syncwarp();
#pragma unroll 4
    for (int l = 0; l < 32; l++) {
        const float* bp = base + l * 512;
        kv2[lane * KV2S + l] = make_float2(bp[o1 + 32 + lane], bp[o2 + 32 + lane]);
    }
    __syncwarp();

    float* out1 = g_bufA + ((size_t)m * 512 + o1) * 32 + lane;
    float* out2 = g_bufA + ((size_t)m * 512 + o2) * 32 + lane;
#pragma unroll 2
    for (int c = 0; c < 32; c++) {
        const float4* rowv = (const float4*)(kv2 + c * KV2S);
        uint64_t a2 = 0ull;
#pragma unroll
        for (int p = 0; p < 16; p++) {
            float4 vv = rowv[p];
            fma2(a2, sim2[2 * p],     pk(vv.x, vv.y));
            fma2(a2, sim2[2 * p + 1], pk(vv.z, vv.w));
        }
        const float* rv = rel_s + (32 + c) * 63 + lane;
        uint64_t e2 = 0ull;
#pragma unroll
        for (int j = 0; j < 32; j++) {
            float r = rv[j];
            fma2(e2, sim2[j], pk(r, r));
        }
        float alo, ahi, elo, ehi;
        upk(a2, alo, ahi); upk(e2, elo, ehi);
        out1[(2 * c) * 32]     = alo * inv1;
        out1[(2 * c + 1) * 32] = elo * inv1;
        out2[(2 * c) * 32]     = ahi * inv2;
        out2[(2 * c + 1) * 32] = ehi * inv2;
    }
}

// ---------------- 4) BN partial stats ---------------------------------------------
__global__ __launch_bounds__(256) void k_stats1() {
    const int ch = blockIdx.x, seg = blockIdx.y;
    const int w = threadIdx.x >> 5, lane = threadIdx.x & 31;
    float s = 0.f, q = 0.f;
    const int m0 = seg * 512;
    for (int t = 0; t < 64; t++) {
        const int m = m0 + w + t * 8;
        const float v = g_bufA[((size_t)m * 512 + ch) * 32 + lane];
        s += v; q = fmaf(v, v, q);
    }
#pragma unroll
    for (int o = 16; o; o >>= 1) {
        s += __shfl_down_sync(0xffffffffu, s, o);
        q += __shfl_down_sync(0xffffffffu, q, o);
    }
    __shared__ float ss[8], qs[8];
    if (lane == 0) { ss[w] = s; qs[w] = q; }
    __syncthreads();
    if (threadIdx.x == 0) {
        float S = 0.f, Q = 0.f;
        for (int t = 0; t < 8; t++) { S += ss[t]; Q += qs[t]; }
        g_part[ch * 8 + seg] = make_float2(S, Q);
    }
}

// ---------------- 5) finalize stats ------------------------------------------------
__global__ void k_stats2(const float* __restrict__ gamma, const float* __restrict__ beta) {
    const int ch = blockIdx.x * 32 + threadIdx.x;
    double s = 0.0, q = 0.0;
    for (int t = 0; t < 8; t++) { float2 p = g_part[ch * 8 + t]; s += p.x; q += p.y; }
    const double N = 131072.0;
    const double mean = s / N;
    const double var = q / N - mean * mean;
    const float sc = (float)((double)gamma[ch] * rsqrt(var + 1e-5));
    g_stats[ch] = make_float2(sc, (float)((double)beta[ch] - mean * (double)sc));
}

// ---------------- 6) normalize + pair-sum + transpose out -------------------------
__global__ __launch_bounds__(256) void k_out(float* __restrict__ out) {
    __shared__ float tile[32][33];
    const int u0 = blockIdx.x * 32, c = blockIdx.y, b = blockIdx.z;
    const int tx = threadIdx.x & 31, ty = threadIdx.x >> 5;
    const float2 p0 = g_stats[2 * c], p1 = g_stats[2 * c + 1];
    const float* base = g_bufA + ((size_t)(b * 1024 + u0) * 512 + 2 * c) * 32;
#pragma unroll
    for (int r = 0; r < 4; r++) {
        const int uu = ty + r * 8;
        const float* pp = base + (size_t)uu * 16384;
        tile[uu][tx] = fmaf(pp[tx], p0.x, p0.y) + fmaf(pp[32 + tx], p1.x, p1.y);
    }
    __syncthreads();
    float* op = out + (size_t)(b * 256 + c) * 32768 + u0;
#pragma unroll
    for (int r = 0; r < 4; r++) {
        const int l = ty + r * 8;
        op[(size_t)l * 1024 + tx] = tile[tx][l];
    }
}

extern "C" void kernel_launch(void* const* d_in, const int* in_sizes, int n_in,
                              void* d_out, int out_size) {
    const float* x     = (const float*)d_in[0];
    const float* Wq    = (const float*)d_in[1];
    const float* rel   = (const float*)d_in[2];
    const float* gamma = (const float*)d_in[3];
    const float* beta  = (const float*)d_in[4];
    float* out = (float*)d_out;

    cudaFuncSetAttribute(k_gemm_mma, cudaFuncAttributeMaxDynamicSharedMemorySize, SM_TOTAL);
    cudaFuncSetAttribute(k_attn, cudaFuncAttributeMaxDynamicSharedMemorySize, ATTN_SMEM);

    k_prep_w  <<<512, 256>>>(Wq);
    k_prep_x  <<<dim3(32, 8, 128), 256>>>(x);
    k_gemm_mma<<<dim3(16, 4, 128), 256, SM_TOTAL>>>();
    k_attn    <<<4096, 128, ATTN_SMEM>>>(rel);
    k_stats1  <<<dim3(512, 8), 256>>>();
    k_stats2  <<<16, 32>>>(gamma, beta);
    k_out     <<<dim3(32, 256, 4), 256>>>(out);
}